// round 1
// baseline (speedup 1.0000x reference)
#include <cuda_runtime.h>
#include <math.h>

// Problem constants
#define NBATCH 2
#define HDIM   96
#define WDIM   96
#define CDIM   256
#define NHEADS 8
#define NPTS   25
#define DH     32
#define HIDDIM 1024
#define LQ     (HDIM*WDIM)      // 9216
#define NLTOK  (NBATCH*LQ)      // 18432

// ---------------- scratch (static device globals; no allocation) ----------------
__device__ float g_q   [NLTOK*CDIM];          // LN1(x)
__device__ float g_val [NLTOK*CDIM];          // value in [n, h, l, d] layout
__device__ float g_off [NLTOK*NHEADS*NPTS*2]; // offsets  [token, h, p, 2]
__device__ float g_aw  [NLTOK*NHEADS*NPTS];   // attn logits -> softmax in place
__device__ float g_attn[NLTOK*CDIM];          // sampled+weighted attention
__device__ float g_x1  [NLTOK*CDIM];          // shortcut + out-proj
__device__ float g_q2  [NLTOK*CDIM];          // LN2(x1)
__device__ float g_h1  [NLTOK*HIDDIM];        // gelu(fc1)

// ---------------- LayerNorm: one warp per token (C=256 -> 8 floats/lane) --------
__global__ void __launch_bounds__(256) ln_kernel(const float* __restrict__ x,
                                                 const float* __restrict__ gam,
                                                 const float* __restrict__ bet,
                                                 float* __restrict__ out)
{
    int warp = threadIdx.x >> 5, lane = threadIdx.x & 31;
    int token = blockIdx.x * 8 + warp;
    const float4* x4 = reinterpret_cast<const float4*>(x) + (size_t)token * 64;
    float4 v0 = x4[lane * 2];
    float4 v1 = x4[lane * 2 + 1];
    float s  = v0.x + v0.y + v0.z + v0.w + v1.x + v1.y + v1.z + v1.w;
    float sq = v0.x*v0.x + v0.y*v0.y + v0.z*v0.z + v0.w*v0.w
             + v1.x*v1.x + v1.y*v1.y + v1.z*v1.z + v1.w*v1.w;
#pragma unroll
    for (int o = 16; o > 0; o >>= 1) {
        s  += __shfl_xor_sync(0xffffffffu, s,  o);
        sq += __shfl_xor_sync(0xffffffffu, sq, o);
    }
    float mean = s * (1.0f / CDIM);
    float var  = sq * (1.0f / CDIM) - mean * mean;
    float rstd = rsqrtf(var + 1e-5f);
    const float4* g4 = reinterpret_cast<const float4*>(gam);
    const float4* b4 = reinterpret_cast<const float4*>(bet);
    float4 ga = g4[lane * 2],     ba = b4[lane * 2];
    float4 gb = g4[lane * 2 + 1], bb = b4[lane * 2 + 1];
    float4 r0, r1;
    r0.x = (v0.x - mean) * rstd * ga.x + ba.x;
    r0.y = (v0.y - mean) * rstd * ga.y + ba.y;
    r0.z = (v0.z - mean) * rstd * ga.z + ba.z;
    r0.w = (v0.w - mean) * rstd * ga.w + ba.w;
    r1.x = (v1.x - mean) * rstd * gb.x + bb.x;
    r1.y = (v1.y - mean) * rstd * gb.y + bb.y;
    r1.z = (v1.z - mean) * rstd * gb.z + bb.z;
    r1.w = (v1.w - mean) * rstd * gb.w + bb.w;
    float4* o4 = reinterpret_cast<float4*>(out) + (size_t)token * 64;
    o4[lane * 2]     = r0;
    o4[lane * 2 + 1] = r1;
}

// ---------------- tiled fp32 GEMM: C[M,N] = A[M,K] @ B[K,N] + bias, + epilogue --
// BM=128, BN=64, BK=16, 256 threads, 8x4 per-thread tile.
enum { EP_PLAIN = 0, EP_VALUE = 1, EP_RESID = 2, EP_GELU = 3 };

__device__ __forceinline__ float gelu_exact(float v) {
    return 0.5f * v * (1.0f + erff(v * 0.70710678118654752f));
}

template <int EPI>
__global__ void __launch_bounds__(256) gemm_kernel(const float* __restrict__ A,
                                                   const float* __restrict__ B,
                                                   const float* __restrict__ bias,
                                                   float* __restrict__ Cout,
                                                   const float* __restrict__ Res,
                                                   int Ncols, int K)
{
    __shared__ __align__(16) float As[16][132];  // transposed: As[k][m], padded stride
    __shared__ __align__(16) float Bs[16][64];
    int tid = threadIdx.x;
    int tx = tid & 15;      // n-dim (16 * 4 = 64)
    int ty = tid >> 4;      // m-dim (16 * 8 = 128)
    int m0 = blockIdx.y * 128;
    int n0 = blockIdx.x * 64;

    float acc[8][4];
#pragma unroll
    for (int i = 0; i < 8; i++)
#pragma unroll
        for (int j = 0; j < 4; j++) acc[i][j] = 0.0f;

    const float* Abase = A + (size_t)m0 * K;
    for (int k0 = 0; k0 < K; k0 += 16) {
        // A tile: 128x16 = 512 float4, 2 per thread, store transposed
#pragma unroll
        for (int i = tid; i < 512; i += 256) {
            int row = i >> 2;
            int c4  = (i & 3) << 2;
            float4 v = *reinterpret_cast<const float4*>(Abase + (size_t)row * K + k0 + c4);
            As[c4 + 0][row] = v.x;
            As[c4 + 1][row] = v.y;
            As[c4 + 2][row] = v.z;
            As[c4 + 3][row] = v.w;
        }
        // B tile: 16x64 = 256 float4, 1 per thread (guarded; Ncols % 4 == 0 always)
        {
            int row = tid >> 4;
            int c4  = (tid & 15) << 2;
            int col = n0 + c4;
            float4 v = make_float4(0.f, 0.f, 0.f, 0.f);
            if (col < Ncols)
                v = *reinterpret_cast<const float4*>(B + (size_t)(k0 + row) * Ncols + col);
            *reinterpret_cast<float4*>(&Bs[row][c4]) = v;
        }
        __syncthreads();
#pragma unroll
        for (int k = 0; k < 16; k++) {
            float4 a0 = *reinterpret_cast<const float4*>(&As[k][ty * 8]);
            float4 a1 = *reinterpret_cast<const float4*>(&As[k][ty * 8 + 4]);
            float4 b0 = *reinterpret_cast<const float4*>(&Bs[k][tx * 4]);
            float av[8] = {a0.x, a0.y, a0.z, a0.w, a1.x, a1.y, a1.z, a1.w};
            float bv[4] = {b0.x, b0.y, b0.z, b0.w};
#pragma unroll
            for (int i = 0; i < 8; i++)
#pragma unroll
                for (int j = 0; j < 4; j++)
                    acc[i][j] = fmaf(av[i], bv[j], acc[i][j]);
        }
        __syncthreads();
    }

    int col = n0 + tx * 4;
    if (col >= Ncols) return;
    float4 bi = *reinterpret_cast<const float4*>(bias + col);
#pragma unroll
    for (int i = 0; i < 8; i++) {
        int row = m0 + ty * 8 + i;
        float4 v;
        v.x = acc[i][0] + bi.x;
        v.y = acc[i][1] + bi.y;
        v.z = acc[i][2] + bi.z;
        v.w = acc[i][3] + bi.w;
        if (EPI == EP_RESID) {
            float4 r = *reinterpret_cast<const float4*>(Res + (size_t)row * Ncols + col);
            v.x += r.x; v.y += r.y; v.z += r.z; v.w += r.w;
        }
        if (EPI == EP_GELU) {
            v.x = gelu_exact(v.x); v.y = gelu_exact(v.y);
            v.z = gelu_exact(v.z); v.w = gelu_exact(v.w);
        }
        if (EPI == EP_VALUE) {
            // scatter col = h*32+d of token row into value[n, h, l, d]
            int n = row / LQ, l = row - n * LQ;
            int h = col >> 5, d = col & 31;
            *reinterpret_cast<float4*>(Cout + ((size_t)((n * NHEADS + h) * LQ + l)) * DH + d) = v;
        } else {
            *reinterpret_cast<float4*>(Cout + (size_t)row * Ncols + col) = v;
        }
    }
}

// ---------------- softmax over P=25 per (token, head): one warp per row --------
__global__ void __launch_bounds__(256) softmax_kernel(float* __restrict__ aw)
{
    int warp = threadIdx.x >> 5, lane = threadIdx.x & 31;
    size_t row = (size_t)blockIdx.x * 8 + warp;    // NLTOK*NHEADS rows
    float* p = aw + row * NPTS;
    float v = (lane < NPTS) ? p[lane] : -1e30f;
    float m = v;
#pragma unroll
    for (int o = 16; o > 0; o >>= 1) m = fmaxf(m, __shfl_xor_sync(0xffffffffu, m, o));
    float e = (lane < NPTS) ? expf(v - m) : 0.0f;
    float s = e;
#pragma unroll
    for (int o = 16; o > 0; o >>= 1) s += __shfl_xor_sync(0xffffffffu, s, o);
    if (lane < NPTS) p[lane] = e / s;
}

// ---------------- deformable sampling: one warp per (token, head), lane = d ----
__global__ void __launch_bounds__(256) sample_kernel(const float* __restrict__ refp)
{
    int warpId = blockIdx.x * 8 + (threadIdx.x >> 5);  // < NLTOK*NHEADS
    int lane = threadIdx.x & 31;
    int token = warpId >> 3;
    int h = warpId & 7;
    int n = token / LQ;
    float rx = __ldg(refp + (size_t)token * 2);
    float ry = __ldg(refp + (size_t)token * 2 + 1);
    const float* offp = g_off + (size_t)token * (NHEADS * NPTS * 2) + h * (NPTS * 2);
    const float* awp  = g_aw  + (size_t)token * (NHEADS * NPTS)     + h * NPTS;
    const float* vb   = g_val + ((size_t)(n * NHEADS + h) * LQ) * DH + lane;
    float acc = 0.0f;
    for (int p = 0; p < NPTS; p++) {
        float ox = __ldg(offp + 2 * p);
        float oy = __ldg(offp + 2 * p + 1);
        float a  = __ldg(awp + p);
        // loc = ref + off/[W,H]; gx = loc_x*W - 0.5 = ref_x*W + off_x - 0.5
        float gx = fmaf(rx, (float)WDIM, ox) - 0.5f;
        float gy = fmaf(ry, (float)HDIM, oy) - 0.5f;
        float fx0 = floorf(gx), fy0 = floorf(gy);
        float fx = gx - fx0, fy = gy - fy0;
        int x0 = (int)fx0, y0 = (int)fy0;
        float w00 = (1.f - fx) * (1.f - fy) * a;
        float w10 = fx * (1.f - fy) * a;
        float w01 = (1.f - fx) * fy * a;
        float w11 = fx * fy * a;
        bool xv0 = (x0 >= 0) && (x0 <= WDIM - 1);
        bool xv1 = (x0 + 1 >= 0) && (x0 + 1 <= WDIM - 1);
        bool yv0 = (y0 >= 0) && (y0 <= HDIM - 1);
        bool yv1 = (y0 + 1 >= 0) && (y0 + 1 <= HDIM - 1);
        if (xv0 && yv0) acc = fmaf(w00, vb[(size_t)(y0 * WDIM + x0) * DH], acc);
        if (xv1 && yv0) acc = fmaf(w10, vb[(size_t)(y0 * WDIM + x0 + 1) * DH], acc);
        if (xv0 && yv1) acc = fmaf(w01, vb[(size_t)((y0 + 1) * WDIM + x0) * DH], acc);
        if (xv1 && yv1) acc = fmaf(w11, vb[(size_t)((y0 + 1) * WDIM + x0 + 1) * DH], acc);
    }
    g_attn[(size_t)token * CDIM + h * DH + lane] = acc;
}

// ---------------- launch ----------------
extern "C" void kernel_launch(void* const* d_in, const int* in_sizes, int n_in,
                              void* d_out, int out_size)
{
    (void)in_sizes; (void)n_in; (void)out_size;
    const float* x      = (const float*)d_in[0];
    const float* refp   = (const float*)d_in[1];
    // d_in[2] spatial_shapes, d_in[3] level_start_index: constants, unused
    const float* ln1g   = (const float*)d_in[4];
    const float* ln1b   = (const float*)d_in[5];
    const float* w_off  = (const float*)d_in[6];
    const float* b_off  = (const float*)d_in[7];
    const float* w_attn = (const float*)d_in[8];
    const float* b_attn = (const float*)d_in[9];
    const float* w_val  = (const float*)d_in[10];
    const float* b_val  = (const float*)d_in[11];
    const float* w_out  = (const float*)d_in[12];
    const float* b_out  = (const float*)d_in[13];
    const float* ln2g   = (const float*)d_in[14];
    const float* ln2b   = (const float*)d_in[15];
    const float* w_fc1  = (const float*)d_in[16];
    const float* b_fc1  = (const float*)d_in[17];
    const float* w_fc2  = (const float*)d_in[18];
    const float* b_fc2  = (const float*)d_in[19];
    float* out = (float*)d_out;

    float *pq, *pval, *poff, *paw, *pattn, *px1, *pq2, *ph1;
    cudaGetSymbolAddress((void**)&pq,    g_q);
    cudaGetSymbolAddress((void**)&pval,  g_val);
    cudaGetSymbolAddress((void**)&poff,  g_off);
    cudaGetSymbolAddress((void**)&paw,   g_aw);
    cudaGetSymbolAddress((void**)&pattn, g_attn);
    cudaGetSymbolAddress((void**)&px1,   g_x1);
    cudaGetSymbolAddress((void**)&pq2,   g_q2);
    cudaGetSymbolAddress((void**)&ph1,   g_h1);

    dim3 blk(256);
    const int MT = NLTOK / 128;  // 144 m-tiles

    ln_kernel<<<NLTOK / 8, blk>>>(x, ln1g, ln1b, pq);
    gemm_kernel<EP_VALUE><<<dim3(4,  MT), blk>>>(pq, w_val,  b_val,  pval,  nullptr, 256,  256);
    gemm_kernel<EP_PLAIN><<<dim3(7,  MT), blk>>>(pq, w_off,  b_off,  poff,  nullptr, 400,  256);
    gemm_kernel<EP_PLAIN><<<dim3(4,  MT), blk>>>(pq, w_attn, b_attn, paw,   nullptr, 200,  256);
    softmax_kernel<<<(NLTOK * NHEADS) / 8, blk>>>(paw);
    sample_kernel<<<(NLTOK * NHEADS) / 8, blk>>>(refp);
    gemm_kernel<EP_RESID><<<dim3(4,  MT), blk>>>(pattn, w_out, b_out, px1, x,   256,  256);
    ln_kernel<<<NLTOK / 8, blk>>>(px1, ln2g, ln2b, pq2);
    gemm_kernel<EP_GELU><<<dim3(16, MT), blk>>>(pq2, w_fc1, b_fc1, ph1, nullptr, 1024, 256);
    gemm_kernel<EP_RESID><<<dim3(4,  MT), blk>>>(ph1, w_fc2, b_fc2, out, px1,    256, 1024);
}

// round 3
// speedup vs baseline: 1.8656x; 1.8656x over previous
#include <cuda_runtime.h>
#include <cuda_bf16.h>
#include <cstdint>
#include <math.h>

// Problem constants
#define NBATCH 2
#define HDIM   96
#define WDIM   96
#define CDIM   256
#define NHEADS 8
#define NPTS   25
#define DH     32
#define HIDDIM 1024
#define LQ     (HDIM*WDIM)      // 9216
#define NLTOK  (NBATCH*LQ)      // 18432

// ================= scratch (device globals, no allocation) =================
__device__ __align__(16) __nv_bfloat16 g_qhi  [NLTOK*CDIM];
__device__ __align__(16) __nv_bfloat16 g_qlo  [NLTOK*CDIM];
__device__ __align__(16) __nv_bfloat16 g_athi [NLTOK*CDIM];
__device__ __align__(16) __nv_bfloat16 g_atlo [NLTOK*CDIM];
__device__ __align__(16) __nv_bfloat16 g_q2hi [NLTOK*CDIM];
__device__ __align__(16) __nv_bfloat16 g_q2lo [NLTOK*CDIM];
__device__ __align__(16) __nv_bfloat16 g_h1hi [NLTOK*HIDDIM];
__device__ __align__(16) __nv_bfloat16 g_h1lo [NLTOK*HIDDIM];
__device__ __align__(16) float g_val [NLTOK*CDIM];           // [n,h,l,d]
__device__ __align__(16) float g_off [NLTOK*NHEADS*NPTS*2];
__device__ __align__(16) float g_aw  [NLTOK*NHEADS*NPTS];
__device__ __align__(16) float g_x1  [NLTOK*CDIM];
// transposed + split + padded weights: [Npad][K] bf16
__device__ __align__(16) __nv_bfloat16 g_wvhi [256*256],   g_wvlo [256*256];
__device__ __align__(16) __nv_bfloat16 g_wohi [512*256],   g_wolo [512*256];
__device__ __align__(16) __nv_bfloat16 g_wahi [256*256],   g_walo [256*256];
__device__ __align__(16) __nv_bfloat16 g_wuhi [256*256],   g_wulo [256*256];
__device__ __align__(16) __nv_bfloat16 g_w1hi [1024*256],  g_w1lo [1024*256];
__device__ __align__(16) __nv_bfloat16 g_w2hi [256*1024],  g_w2lo [256*1024];

// ================= low-level helpers (arch-agnostic PTX only) ==============
__device__ __forceinline__ uint32_t smem_u32(const void* p) {
    uint32_t a;
    asm("{ .reg .u64 t; cvta.to.shared.u64 t, %1; cvt.u32.u64 %0, t; }" : "=r"(a) : "l"(p));
    return a;
}
__device__ __forceinline__ void cp16(uint32_t s, const void* g) {
    asm volatile("cp.async.cg.shared.global [%0], [%1], 16;" :: "r"(s), "l"(g));
}
#define CP_COMMIT() asm volatile("cp.async.commit_group;" ::: "memory")
#define CP_WAIT(n)  asm volatile("cp.async.wait_group %0;" :: "n"(n) : "memory")

__device__ __forceinline__ void ldm4(uint32_t* r, uint32_t addr) {
    asm volatile("ldmatrix.sync.aligned.m8n8.x4.shared.b16 {%0,%1,%2,%3}, [%4];"
                 : "=r"(r[0]), "=r"(r[1]), "=r"(r[2]), "=r"(r[3]) : "r"(addr));
}
__device__ __forceinline__ void mma_bf16(float* d, const uint32_t* a, const uint32_t* b) {
    asm volatile("mma.sync.aligned.m16n8k16.row.col.f32.bf16.bf16.f32 "
                 "{%0,%1,%2,%3}, {%4,%5,%6,%7}, {%8,%9}, {%0,%1,%2,%3};"
                 : "+f"(d[0]), "+f"(d[1]), "+f"(d[2]), "+f"(d[3])
                 : "r"(a[0]), "r"(a[1]), "r"(a[2]), "r"(a[3]), "r"(b[0]), "r"(b[1]));
}

// ================= weight prep: W[K,N] -> Wt_{hi,lo}[Npad][K] ===============
__global__ void __launch_bounds__(256) wprep_kernel(const float* __restrict__ W,
                                                    __nv_bfloat16* __restrict__ Whi,
                                                    __nv_bfloat16* __restrict__ Wlo,
                                                    int K, int N, int Npad)
{
    int idx = blockIdx.x * 256 + threadIdx.x;
    if (idx >= Npad * K) return;
    int n = idx / K, k = idx - n * K;
    float v = (n < N) ? W[(size_t)k * N + n] : 0.0f;
    __nv_bfloat16 hi = __float2bfloat16(v);
    __nv_bfloat16 lo = __float2bfloat16(v - __bfloat162float(hi));
    Whi[idx] = hi;
    Wlo[idx] = lo;
}

// ================= LayerNorm: warp/token, outputs bf16 hi/lo ================
__global__ void __launch_bounds__(256) ln_kernel(const float* __restrict__ x,
                                                 const float* __restrict__ gam,
                                                 const float* __restrict__ bet,
                                                 __nv_bfloat16* __restrict__ ohi,
                                                 __nv_bfloat16* __restrict__ olo)
{
    int warp = threadIdx.x >> 5, lane = threadIdx.x & 31;
    int token = blockIdx.x * 8 + warp;
    const float4* x4 = reinterpret_cast<const float4*>(x) + (size_t)token * 64;
    float4 v0 = x4[lane * 2];
    float4 v1 = x4[lane * 2 + 1];
    float s  = v0.x + v0.y + v0.z + v0.w + v1.x + v1.y + v1.z + v1.w;
    float sq = v0.x*v0.x + v0.y*v0.y + v0.z*v0.z + v0.w*v0.w
             + v1.x*v1.x + v1.y*v1.y + v1.z*v1.z + v1.w*v1.w;
#pragma unroll
    for (int o = 16; o > 0; o >>= 1) {
        s  += __shfl_xor_sync(0xffffffffu, s,  o);
        sq += __shfl_xor_sync(0xffffffffu, sq, o);
    }
    float mean = s * (1.0f / CDIM);
    float var  = sq * (1.0f / CDIM) - mean * mean;
    float rstd = rsqrtf(var + 1e-5f);
    const float4* g4 = reinterpret_cast<const float4*>(gam);
    const float4* b4 = reinterpret_cast<const float4*>(bet);
    float r[8];
    {
        float4 ga = g4[lane * 2],     ba = b4[lane * 2];
        float4 gb = g4[lane * 2 + 1], bb = b4[lane * 2 + 1];
        r[0] = (v0.x - mean) * rstd * ga.x + ba.x;
        r[1] = (v0.y - mean) * rstd * ga.y + ba.y;
        r[2] = (v0.z - mean) * rstd * ga.z + ba.z;
        r[3] = (v0.w - mean) * rstd * ga.w + ba.w;
        r[4] = (v1.x - mean) * rstd * gb.x + bb.x;
        r[5] = (v1.y - mean) * rstd * gb.y + bb.y;
        r[6] = (v1.z - mean) * rstd * gb.z + bb.z;
        r[7] = (v1.w - mean) * rstd * gb.w + bb.w;
    }
    size_t base = (size_t)token * CDIM + lane * 8;
#pragma unroll
    for (int i = 0; i < 8; i += 2) {
        __nv_bfloat16 h0 = __float2bfloat16(r[i]);
        __nv_bfloat16 h1 = __float2bfloat16(r[i + 1]);
        __nv_bfloat16 l0 = __float2bfloat16(r[i] - __bfloat162float(h0));
        __nv_bfloat16 l1 = __float2bfloat16(r[i + 1] - __bfloat162float(h1));
        *reinterpret_cast<__nv_bfloat162*>(ohi + base + i) = __nv_bfloat162(h0, h1);
        *reinterpret_cast<__nv_bfloat162*>(olo + base + i) = __nv_bfloat162(l0, l1);
    }
}

// ================= warp-MMA GEMM =================
// D[M,N] = (Ahi+Alo)[M,K] @ (Bhi+Blo)[N,K]^T   (3-term bf16 split, fp32 acc)
// BM=128, BN=64, BK=32, 256 thr (8 warps, 4x2), 2-stage cp.async pipeline.
// smem rows: 128B = [hi 4x16B | lo 4x16B], XOR-swizzled (c ^= row&7).
enum { EP_VALUE = 0, EP_PLAIN = 1, EP_RESID = 2, EP_GELU = 3 };

__device__ __forceinline__ float gelu_exact(float v) {
    return 0.5f * v * (1.0f + erff(v * 0.70710678118654752f));
}

#define STAGE_BYTES 24576        // A 16KB + B 8KB
#define B_OFF       16384

template <int EPI>
__global__ void __launch_bounds__(256) mm_mma(const __nv_bfloat16* __restrict__ Ahi,
                                              const __nv_bfloat16* __restrict__ Alo,
                                              const __nv_bfloat16* __restrict__ Bhi,
                                              const __nv_bfloat16* __restrict__ Blo,
                                              const float* __restrict__ bias,
                                              float* __restrict__ Cout,
                                              const float* __restrict__ Res,
                                              __nv_bfloat16* __restrict__ OutHi,
                                              __nv_bfloat16* __restrict__ OutLo,
                                              int K, int Nvalid, int ldc)
{
    extern __shared__ __align__(128) char smem[];
    const uint32_t sb = smem_u32(smem);
    const int tid = threadIdx.x;
    const int wid = tid >> 5, l = tid & 31;
    const int wm = wid & 3, wn = wid >> 2;
    const int m0 = blockIdx.y * 128, n0 = blockIdx.x * 64;

    float acc[2][4][4];
#pragma unroll
    for (int i = 0; i < 2; i++)
#pragma unroll
        for (int j = 0; j < 4; j++)
#pragma unroll
            for (int q = 0; q < 4; q++) acc[i][j][q] = 0.0f;

    // ---- loader lambda-ish macro state ----
    const int lr_a = tid >> 3;           // 0..31 (row step 32)
    const int lc   = tid & 7;            // chunk 0..7
    const int KC = K >> 5;

    // prologue: stage 0
    {
        uint32_t ab = sb;
#pragma unroll
        for (int i = 0; i < 4; i++) {
            int r = i * 32 + lr_a;
            const __nv_bfloat16* src = (lc < 4 ? Ahi : Alo) + (size_t)(m0 + r) * K + (lc & 3) * 8;
            cp16(ab + r * 128 + ((lc ^ (r & 7)) << 4), src);
        }
        uint32_t bb = sb + B_OFF;
#pragma unroll
        for (int i = 0; i < 2; i++) {
            int r = i * 32 + lr_a;
            const __nv_bfloat16* src = (lc < 4 ? Bhi : Blo) + (size_t)(n0 + r) * K + (lc & 3) * 8;
            cp16(bb + r * 128 + ((lc ^ (r & 7)) << 4), src);
        }
        CP_COMMIT();
    }

    // per-thread ldmatrix base offsets
    const int rowA = wm * 32 + (l & 15);           // + mt*16
    const int cxA  = (l >> 4);                     // 0/1
    const int rowB = wn * 32 + (l & 7) + ((l >> 4) << 3);  // + ntp*16
    const int cxB  = (l >> 3) & 1;
    const int swzA = rowA & 7;
    const int swzB = rowB & 7;

    for (int kc = 0; kc < KC; kc++) {
        if (kc + 1 < KC) {
            int k0 = (kc + 1) << 5;
            uint32_t ab = sb + ((kc + 1) & 1) * STAGE_BYTES;
#pragma unroll
            for (int i = 0; i < 4; i++) {
                int r = i * 32 + lr_a;
                const __nv_bfloat16* src = (lc < 4 ? Ahi : Alo) + (size_t)(m0 + r) * K + k0 + (lc & 3) * 8;
                cp16(ab + r * 128 + ((lc ^ (r & 7)) << 4), src);
            }
            uint32_t bb = ab + B_OFF;
#pragma unroll
            for (int i = 0; i < 2; i++) {
                int r = i * 32 + lr_a;
                const __nv_bfloat16* src = (lc < 4 ? Bhi : Blo) + (size_t)(n0 + r) * K + k0 + (lc & 3) * 8;
                cp16(bb + r * 128 + ((lc ^ (r & 7)) << 4), src);
            }
            CP_COMMIT();
            CP_WAIT(1);
        } else {
            CP_WAIT(0);
        }
        __syncthreads();

        uint32_t ab = sb + (kc & 1) * STAGE_BYTES;
        uint32_t bb = ab + B_OFF;
#pragma unroll
        for (int ks = 0; ks < 2; ks++) {
            uint32_t a_hi[2][4], a_lo[2][4], b_hi[2][4], b_lo[2][4];
#pragma unroll
            for (int mt = 0; mt < 2; mt++) {
                int row = rowA + mt * 16;
                uint32_t base = ab + row * 128;
                int c_hi = ks * 2 + cxA;
                ldm4(a_hi[mt], base + (((c_hi)     ^ swzA) << 4));
                ldm4(a_lo[mt], base + (((c_hi + 4) ^ swzA) << 4));
            }
#pragma unroll
            for (int ntp = 0; ntp < 2; ntp++) {     // each covers 16 n (2 mma n-tiles)
                int row = rowB + ntp * 16;
                uint32_t base = bb + row * 128;
                int c_hi = ks * 2 + cxB;
                ldm4(b_hi[ntp], base + (((c_hi)     ^ swzB) << 4));
                ldm4(b_lo[ntp], base + (((c_hi + 4) ^ swzB) << 4));
            }
#pragma unroll
            for (int mt = 0; mt < 2; mt++)
#pragma unroll
                for (int nt = 0; nt < 4; nt++) {
                    const uint32_t* bh = &b_hi[nt >> 1][(nt & 1) * 2];
                    const uint32_t* bl = &b_lo[nt >> 1][(nt & 1) * 2];
                    mma_bf16(acc[mt][nt], a_hi[mt], bh);
                    mma_bf16(acc[mt][nt], a_hi[mt], bl);
                    mma_bf16(acc[mt][nt], a_lo[mt], bh);
                }
        }
        __syncthreads();
    }

    // ---- epilogue: thread t holds rows (base + l/4, +8), cols (base + (l%4)*2, +1)
#pragma unroll
    for (int mt = 0; mt < 2; mt++) {
#pragma unroll
        for (int nt = 0; nt < 4; nt++) {
            int col = n0 + wn * 32 + nt * 8 + (l & 3) * 2;
            if (col >= Nvalid) continue;
            float2 bv = *reinterpret_cast<const float2*>(bias + col);
#pragma unroll
            for (int half = 0; half < 2; half++) {
                int row = m0 + wm * 32 + mt * 16 + (l >> 2) + half * 8;
                float v0 = acc[mt][nt][half * 2]     + bv.x;
                float v1 = acc[mt][nt][half * 2 + 1] + bv.y;
                if (EPI == EP_RESID) {
                    float2 r = *reinterpret_cast<const float2*>(Res + (size_t)row * ldc + col);
                    v0 += r.x; v1 += r.y;
                }
                if (EPI == EP_GELU) {
                    v0 = gelu_exact(v0);
                    v1 = gelu_exact(v1);
                    __nv_bfloat16 h0 = __float2bfloat16(v0), h1 = __float2bfloat16(v1);
                    __nv_bfloat16 l0 = __float2bfloat16(v0 - __bfloat162float(h0));
                    __nv_bfloat16 l1 = __float2bfloat16(v1 - __bfloat162float(h1));
                    size_t o = (size_t)row * ldc + col;
                    *reinterpret_cast<__nv_bfloat162*>(OutHi + o) = __nv_bfloat162(h0, h1);
                    *reinterpret_cast<__nv_bfloat162*>(OutLo + o) = __nv_bfloat162(l0, l1);
                } else if (EPI == EP_VALUE) {
                    int n = row / LQ, li = row - n * LQ;
                    int h = col >> 5, d = col & 31;
                    *reinterpret_cast<float2*>(Cout +
                        ((size_t)((n * NHEADS + h) * LQ + li)) * DH + d) = make_float2(v0, v1);
                } else {
                    *reinterpret_cast<float2*>(Cout + (size_t)row * ldc + col) = make_float2(v0, v1);
                }
            }
        }
    }
}

// ================= softmax over P=25: one warp per (token, head) ============
__global__ void __launch_bounds__(256) softmax_kernel(float* __restrict__ aw)
{
    int warp = threadIdx.x >> 5, lane = threadIdx.x & 31;
    size_t row = (size_t)blockIdx.x * 8 + warp;
    float* p = aw + row * NPTS;
    float v = (lane < NPTS) ? p[lane] : -1e30f;
    float mx = v;
#pragma unroll
    for (int o = 16; o > 0; o >>= 1) mx = fmaxf(mx, __shfl_xor_sync(0xffffffffu, mx, o));
    float e = (lane < NPTS) ? expf(v - mx) : 0.0f;
    float s = e;
#pragma unroll
    for (int o = 16; o > 0; o >>= 1) s += __shfl_xor_sync(0xffffffffu, s, o);
    if (lane < NPTS) p[lane] = e / s;
}

// ================= deformable sampling: warp per (token, head), lane = d ====
__global__ void __launch_bounds__(256) sample_kernel(const float* __restrict__ refp)
{
    int warpId = blockIdx.x * 8 + (threadIdx.x >> 5);
    int lane = threadIdx.x & 31;
    int token = warpId >> 3;
    int h = warpId & 7;
    int n = token / LQ;
    float rx = __ldg(refp + (size_t)token * 2);
    float ry = __ldg(refp + (size_t)token * 2 + 1);
    const float* offp = g_off + (size_t)token * (NHEADS * NPTS * 2) + h * (NPTS * 2);
    const float* awp  = g_aw  + (size_t)token * (NHEADS * NPTS)     + h * NPTS;
    const float* vb   = g_val + ((size_t)(n * NHEADS + h) * LQ) * DH + lane;
    float acc = 0.0f;
    for (int p = 0; p < NPTS; p++) {
        float ox = __ldg(offp + 2 * p);
        float oy = __ldg(offp + 2 * p + 1);
        float a  = __ldg(awp + p);
        float gx = fmaf(rx, (float)WDIM, ox) - 0.5f;
        float gy = fmaf(ry, (float)HDIM, oy) - 0.5f;
        float fx0 = floorf(gx), fy0 = floorf(gy);
        float fx = gx - fx0, fy = gy - fy0;
        int x0 = (int)fx0, y0 = (int)fy0;
        float w00 = (1.f - fx) * (1.f - fy) * a;
        float w10 = fx * (1.f - fy) * a;
        float w01 = (1.f - fx) * fy * a;
        float w11 = fx * fy * a;
        bool xv0 = (x0 >= 0) && (x0 < WDIM);
        bool xv1 = (x0 + 1 >= 0) && (x0 + 1 < WDIM);
        bool yv0 = (y0 >= 0) && (y0 < HDIM);
        bool yv1 = (y0 + 1 >= 0) && (y0 + 1 < HDIM);
        if (xv0 && yv0) acc = fmaf(w00, vb[(size_t)(y0 * WDIM + x0) * DH], acc);
        if (xv1 && yv0) acc = fmaf(w10, vb[(size_t)(y0 * WDIM + x0 + 1) * DH], acc);
        if (xv0 && yv1) acc = fmaf(w01, vb[(size_t)((y0 + 1) * WDIM + x0) * DH], acc);
        if (xv1 && yv1) acc = fmaf(w11, vb[(size_t)((y0 + 1) * WDIM + x0 + 1) * DH], acc);
    }
    __nv_bfloat16 hi = __float2bfloat16(acc);
    __nv_bfloat16 lo = __float2bfloat16(acc - __bfloat162float(hi));
    size_t o = (size_t)token * CDIM + h * DH + lane;
    g_athi[o] = hi;
    g_atlo[o] = lo;
}

// ================= launch =================
extern "C" void kernel_launch(void* const* d_in, const int* in_sizes, int n_in,
                              void* d_out, int out_size)
{
    (void)in_sizes; (void)n_in; (void)out_size;
    const float* x      = (const float*)d_in[0];
    const float* refp   = (const float*)d_in[1];
    const float* ln1g   = (const float*)d_in[4];
    const float* ln1b   = (const float*)d_in[5];
    const float* w_off  = (const float*)d_in[6];
    const float* b_off  = (const float*)d_in[7];
    const float* w_attn = (const float*)d_in[8];
    const float* b_attn = (const float*)d_in[9];
    const float* w_val  = (const float*)d_in[10];
    const float* b_val  = (const float*)d_in[11];
    const float* w_out  = (const float*)d_in[12];
    const float* b_out  = (const float*)d_in[13];
    const float* ln2g   = (const float*)d_in[14];
    const float* ln2b   = (const float*)d_in[15];
    const float* w_fc1  = (const float*)d_in[16];
    const float* b_fc1  = (const float*)d_in[17];
    const float* w_fc2  = (const float*)d_in[18];
    const float* b_fc2  = (const float*)d_in[19];
    float* out = (float*)d_out;

    __nv_bfloat16 *qhi, *qlo, *athi, *atlo, *q2hi, *q2lo, *h1hi, *h1lo;
    __nv_bfloat16 *wvhi, *wvlo, *wohi, *wolo, *wahi, *walo, *wuhi, *wulo, *w1hi, *w1lo, *w2hi, *w2lo;
    float *pval, *poff, *paw, *px1;
    cudaGetSymbolAddress((void**)&qhi,  g_qhi);  cudaGetSymbolAddress((void**)&qlo,  g_qlo);
    cudaGetSymbolAddress((void**)&athi, g_athi); cudaGetSymbolAddress((void**)&atlo, g_atlo);
    cudaGetSymbolAddress((void**)&q2hi, g_q2hi); cudaGetSymbolAddress((void**)&q2lo, g_q2lo);
    cudaGetSymbolAddress((void**)&h1hi, g_h1hi); cudaGetSymbolAddress((void**)&h1lo, g_h1lo);
    cudaGetSymbolAddress((void**)&wvhi, g_wvhi); cudaGetSymbolAddress((void**)&wvlo, g_wvlo);
    cudaGetSymbolAddress((void**)&wohi, g_wohi); cudaGetSymbolAddress((void**)&wolo, g_wolo);
    cudaGetSymbolAddress((void**)&wahi, g_wahi); cudaGetSymbolAddress((void**)&walo, g_walo);
    cudaGetSymbolAddress((void**)&wuhi, g_wuhi); cudaGetSymbolAddress((void**)&wulo, g_wulo);
    cudaGetSymbolAddress((void**)&w1hi, g_w1hi); cudaGetSymbolAddress((void**)&w1lo, g_w1lo);
    cudaGetSymbolAddress((void**)&w2hi, g_w2hi); cudaGetSymbolAddress((void**)&w2lo, g_w2lo);
    cudaGetSymbolAddress((void**)&pval, g_val);
    cudaGetSymbolAddress((void**)&poff, g_off);
    cudaGetSymbolAddress((void**)&paw,  g_aw);
    cudaGetSymbolAddress((void**)&px1,  g_x1);

    const int SM_TOT = 2 * STAGE_BYTES;   // 48KB
    cudaFuncSetAttribute(mm_mma<EP_VALUE>, cudaFuncAttributeMaxDynamicSharedMemorySize, SM_TOT);
    cudaFuncSetAttribute(mm_mma<EP_PLAIN>, cudaFuncAttributeMaxDynamicSharedMemorySize, SM_TOT);
    cudaFuncSetAttribute(mm_mma<EP_RESID>, cudaFuncAttributeMaxDynamicSharedMemorySize, SM_TOT);
    cudaFuncSetAttribute(mm_mma<EP_GELU>,  cudaFuncAttributeMaxDynamicSharedMemorySize, SM_TOT);

    dim3 blk(256);
    const int MT = NLTOK / 128;   // 144

    // weight prep (transpose + bf16 split + pad)
    wprep_kernel<<<(256*256  + 255)/256, blk>>>(w_val,  wvhi, wvlo, 256,  256,  256);
    wprep_kernel<<<(512*256  + 255)/256, blk>>>(w_off,  wohi, wolo, 256,  400,  512);
    wprep_kernel<<<(256*256  + 255)/256, blk>>>(w_attn, wahi, walo, 256,  200,  256);
    wprep_kernel<<<(256*256  + 255)/256, blk>>>(w_out,  wuhi, wulo, 256,  256,  256);
    wprep_kernel<<<(1024*256 + 255)/256, blk>>>(w_fc1,  w1hi, w1lo, 256,  1024, 1024);
    wprep_kernel<<<(256*1024 + 255)/256, blk>>>(w_fc2,  w2hi, w2lo, 1024, 256,  256);

    ln_kernel<<<NLTOK / 8, blk>>>(x, ln1g, ln1b, qhi, qlo);

    mm_mma<EP_VALUE><<<dim3(4,  MT), blk, SM_TOT>>>(qhi, qlo, wvhi, wvlo, b_val,  pval, nullptr,
                                                    nullptr, nullptr, 256, 256, 256);
    mm_mma<EP_PLAIN><<<dim3(7,  MT), blk, SM_TOT>>>(qhi, qlo, wohi, wolo, b_off,  poff, nullptr,
                                                    nullptr, nullptr, 256, 400, 400);
    mm_mma<EP_PLAIN><<<dim3(4,  MT), blk, SM_TOT>>>(qhi, qlo, wahi, walo, b_attn, paw,  nullptr,
                                                    nullptr, nullptr, 256, 200, 200);
    softmax_kernel<<<(NLTOK * NHEADS) / 8, blk>>>(paw);
    sample_kernel<<<(NLTOK * NHEADS) / 8, blk>>>(refp);
    mm_mma<EP_RESID><<<dim3(4,  MT), blk, SM_TOT>>>(athi, atlo, wuhi, wulo, b_out, px1, x,
                                                    nullptr, nullptr, 256, 256, 256);
    ln_kernel<<<NLTOK / 8, blk>>>(px1, ln2g, ln2b, q2hi, q2lo);
    mm_mma<EP_GELU><<<dim3(16, MT), blk, SM_TOT>>>(q2hi, q2lo, w1hi, w1lo, b_fc1, nullptr, nullptr,
                                                   h1hi, h1lo, 256, 1024, 1024);
    mm_mma<EP_RESID><<<dim3(4,  MT), blk, SM_TOT>>>(h1hi, h1lo, w2hi, w2lo, b_fc2, out, px1,
                                                    nullptr, nullptr, 1024, 256, 256);
}

// round 5
// speedup vs baseline: 2.3245x; 1.2460x over previous
#include <cuda_runtime.h>
#include <cuda_fp16.h>
#include <cstdint>
#include <math.h>

// Problem constants
#define NBATCH 2
#define HDIM   96
#define WDIM   96
#define CDIM   256
#define NHEADS 8
#define NPTS   25
#define DH     32
#define HIDDIM 1024
#define LQ     (HDIM*WDIM)      // 9216
#define NLTOK  (NBATCH*LQ)      // 18432

// ================= scratch (device globals, no allocation) =================
__device__ __align__(16) __half g_q  [NLTOK*CDIM];      // LN1 out, fp16
__device__ __align__(16) __half g_at [NLTOK*CDIM];      // attention out, fp16
__device__ __align__(16) __half g_q2 [NLTOK*CDIM];      // LN2 out, fp16
__device__ __align__(16) __half g_h1 [NLTOK*HIDDIM];    // gelu(fc1), fp16
__device__ __align__(16) float g_val [NLTOK*CDIM];      // [n,h,l,d]
__device__ __align__(16) float g_off [NLTOK*NHEADS*NPTS*2];
__device__ __align__(16) float g_aw  [NLTOK*NHEADS*NPTS];
__device__ __align__(16) float g_x1  [NLTOK*CDIM];
// transposed + split + padded weights: [Npad][K] fp16 hi/lo
__device__ __align__(16) __half g_wvhi [256*256],   g_wvlo [256*256];
__device__ __align__(16) __half g_wohi [512*256],   g_wolo [512*256];
__device__ __align__(16) __half g_wahi [256*256],   g_walo [256*256];
__device__ __align__(16) __half g_wuhi [256*256],   g_wulo [256*256];
__device__ __align__(16) __half g_w1hi [1024*256],  g_w1lo [1024*256];
__device__ __align__(16) __half g_w2hi [256*1024],  g_w2lo [256*1024];

// ================= low-level helpers (arch-agnostic PTX only) ==============
__device__ __forceinline__ uint32_t smem_u32(const void* p) {
    uint32_t a;
    asm("{ .reg .u64 t; cvta.to.shared.u64 t, %1; cvt.u32.u64 %0, t; }" : "=r"(a) : "l"(p));
    return a;
}
__device__ __forceinline__ void cp16(uint32_t s, const void* g) {
    asm volatile("cp.async.cg.shared.global [%0], [%1], 16;" :: "r"(s), "l"(g));
}
#define CP_COMMIT() asm volatile("cp.async.commit_group;" ::: "memory")
#define CP_WAIT(n)  asm volatile("cp.async.wait_group %0;" :: "n"(n) : "memory")

__device__ __forceinline__ void ldm4(uint32_t* r, uint32_t addr) {
    asm volatile("ldmatrix.sync.aligned.m8n8.x4.shared.b16 {%0,%1,%2,%3}, [%4];"
                 : "=r"(r[0]), "=r"(r[1]), "=r"(r[2]), "=r"(r[3]) : "r"(addr));
}
__device__ __forceinline__ void mma_f16(float* d, const uint32_t* a, const uint32_t* b) {
    asm volatile("mma.sync.aligned.m16n8k16.row.col.f32.f16.f16.f32 "
                 "{%0,%1,%2,%3}, {%4,%5,%6,%7}, {%8,%9}, {%0,%1,%2,%3};"
                 : "+f"(d[0]), "+f"(d[1]), "+f"(d[2]), "+f"(d[3])
                 : "r"(a[0]), "r"(a[1]), "r"(a[2]), "r"(a[3]), "r"(b[0]), "r"(b[1]));
}

// ================= weight prep: W[K,N] -> Wt_{hi,lo}[Npad][K], coalesced =====
__global__ void __launch_bounds__(256) wprep_kernel(const float* __restrict__ W,
                                                    __half* __restrict__ Whi,
                                                    __half* __restrict__ Wlo,
                                                    int K, int N)
{
    __shared__ float s[32][33];
    int tx = threadIdx.x, ty = threadIdx.y;          // (32, 8)
    int k0 = blockIdx.x * 32, n0 = blockIdx.y * 32;
#pragma unroll
    for (int j = ty; j < 32; j += 8) {
        int n = n0 + tx;
        s[j][tx] = (n < N) ? W[(size_t)(k0 + j) * N + n] : 0.0f;
    }
    __syncthreads();
#pragma unroll
    for (int j = ty; j < 32; j += 8) {
        float v = s[tx][j];
        __half hi = __float2half(v);
        __half lo = __float2half(v - __half2float(hi));
        size_t o = (size_t)(n0 + j) * K + k0 + tx;
        Whi[o] = hi;
        Wlo[o] = lo;
    }
}

// ================= LayerNorm: warp/token, fp16 out ==========================
__global__ void __launch_bounds__(256) ln_kernel(const float* __restrict__ x,
                                                 const float* __restrict__ gam,
                                                 const float* __restrict__ bet,
                                                 __half* __restrict__ o)
{
    int warp = threadIdx.x >> 5, lane = threadIdx.x & 31;
    int token = blockIdx.x * 8 + warp;
    const float4* x4 = reinterpret_cast<const float4*>(x) + (size_t)token * 64;
    float4 v0 = x4[lane * 2];
    float4 v1 = x4[lane * 2 + 1];
    float s  = v0.x + v0.y + v0.z + v0.w + v1.x + v1.y + v1.z + v1.w;
    float sq = v0.x*v0.x + v0.y*v0.y + v0.z*v0.z + v0.w*v0.w
             + v1.x*v1.x + v1.y*v1.y + v1.z*v1.z + v1.w*v1.w;
#pragma unroll
    for (int of = 16; of > 0; of >>= 1) {
        s  += __shfl_xor_sync(0xffffffffu, s,  of);
        sq += __shfl_xor_sync(0xffffffffu, sq, of);
    }
    float mean = s * (1.0f / CDIM);
    float var  = sq * (1.0f / CDIM) - mean * mean;
    float rstd = rsqrtf(var + 1e-5f);
    const float4* g4 = reinterpret_cast<const float4*>(gam);
    const float4* b4 = reinterpret_cast<const float4*>(bet);
    float r[8];
    {
        float4 ga = g4[lane * 2],     ba = b4[lane * 2];
        float4 gb = g4[lane * 2 + 1], bb = b4[lane * 2 + 1];
        r[0] = (v0.x - mean) * rstd * ga.x + ba.x;
        r[1] = (v0.y - mean) * rstd * ga.y + ba.y;
        r[2] = (v0.z - mean) * rstd * ga.z + ba.z;
        r[3] = (v0.w - mean) * rstd * ga.w + ba.w;
        r[4] = (v1.x - mean) * rstd * gb.x + bb.x;
        r[5] = (v1.y - mean) * rstd * gb.y + bb.y;
        r[6] = (v1.z - mean) * rstd * gb.z + bb.z;
        r[7] = (v1.w - mean) * rstd * gb.w + bb.w;
    }
    size_t base = (size_t)token * CDIM + lane * 8;
#pragma unroll
    for (int i = 0; i < 8; i += 2)
        *reinterpret_cast<__half2*>(o + base + i) =
            __floats2half2_rn(r[i], r[i + 1]);
}

// ================= warp-MMA GEMM (2-term fp16 weight split) =================
// D[M,N] = A[M,K] @ (Bh+Bl)[N,K]^T, fp32 acc.
// BM=128, BN=64, BK=64, 256 thr (8 warps, 4x2 m-n), 2-stage cp.async.
// smem/stage: A 128x128B (64 fp16/row) = 16KB; Bh 64x128B = 8KB; Bl 8KB.
enum { EP_VALUE = 0, EP_PLAIN = 1, EP_RESID = 2, EP_GELU = 3 };

__device__ __forceinline__ float gelu_exact(float v) {
    return 0.5f * v * (1.0f + erff(v * 0.70710678118654752f));
}

#define STAGE_BYTES 32768
#define BH_OFF      16384
#define BL_OFF      24576

template <int EPI>
__global__ void __launch_bounds__(256) mm_mma(const __half* __restrict__ A,
                                              const __half* __restrict__ Bh,
                                              const __half* __restrict__ Bl,
                                              const float* __restrict__ bias,
                                              float* __restrict__ Cout,
                                              const float* __restrict__ Res,
                                              __half* __restrict__ OutH,
                                              int K, int Nvalid, int ldc)
{
    extern __shared__ __align__(128) char smem[];
    const uint32_t sb = smem_u32(smem);
    const int tid = threadIdx.x;
    const int wid = tid >> 5, l = tid & 31;
    const int wm = wid & 3, wn = wid >> 2;
    const int m0 = blockIdx.y * 128, n0 = blockIdx.x * 64;

    float acc[2][4][4];
#pragma unroll
    for (int i = 0; i < 2; i++)
#pragma unroll
        for (int j = 0; j < 4; j++)
#pragma unroll
            for (int q = 0; q < 4; q++) acc[i][j][q] = 0.0f;

    const int KC = K >> 6;

    // ---- stage loader ----
    auto load_stage = [&](int kcidx) {
        int k0 = kcidx << 6;
        uint32_t st = sb + (kcidx & 1) * STAGE_BYTES;
#pragma unroll
        for (int i = 0; i < 4; i++) {          // A: 1024 16B-chunks
            int id = tid + i * 256;
            int r = id >> 3, c = id & 7;
            cp16(st + r * 128 + ((c ^ (r & 7)) << 4),
                 A + (size_t)(m0 + r) * K + k0 + c * 8);
        }
#pragma unroll
        for (int i = 0; i < 2; i++) {          // Bh + Bl: 512 chunks each
            int id = tid + i * 256;
            int r = id >> 3, c = id & 7;
            uint32_t so = r * 128 + ((c ^ (r & 7)) << 4);
            size_t go = (size_t)(n0 + r) * K + k0 + c * 8;
            cp16(st + BH_OFF + so, Bh + go);
            cp16(st + BL_OFF + so, Bl + go);
        }
        CP_COMMIT();
    };

    load_stage(0);

    // per-thread ldmatrix row/col decomposition
    const int rowA = wm * 32 + (l & 15);
    const int cxA  = l >> 4;
    const int rowB = wn * 32 + (l & 7) + ((l >> 4) << 3);
    const int cxB  = (l >> 3) & 1;

    for (int kc = 0; kc < KC; kc++) {
        if (kc + 1 < KC) {
            load_stage(kc + 1);
            CP_WAIT(1);
        } else {
            CP_WAIT(0);
        }
        __syncthreads();

        uint32_t ab  = sb + (kc & 1) * STAGE_BYTES;
        uint32_t bhb = ab + BH_OFF, blb = ab + BL_OFF;
#pragma unroll
        for (int ks = 0; ks < 4; ks++) {
            uint32_t a[2][4], bh[2][4], bl[2][4];
#pragma unroll
            for (int mt = 0; mt < 2; mt++) {
                int row = rowA + mt * 16;
                ldm4(a[mt], ab + row * 128 + (((ks * 2 + cxA) ^ (row & 7)) << 4));
            }
#pragma unroll
            for (int ntp = 0; ntp < 2; ntp++) {
                int row = rowB + ntp * 16;
                uint32_t so = row * 128 + (((ks * 2 + cxB) ^ (row & 7)) << 4);
                ldm4(bh[ntp], bhb + so);
                ldm4(bl[ntp], blb + so);
            }
#pragma unroll
            for (int mt = 0; mt < 2; mt++)
#pragma unroll
                for (int nt = 0; nt < 4; nt++) {
                    const uint32_t* ph = &bh[nt >> 1][(nt & 1) * 2];
                    const uint32_t* pl = &bl[nt >> 1][(nt & 1) * 2];
                    mma_f16(acc[mt][nt], a[mt], ph);
                    mma_f16(acc[mt][nt], a[mt], pl);
                }
        }
        __syncthreads();
    }

    // ---- epilogue ----
#pragma unroll
    for (int mt = 0; mt < 2; mt++) {
#pragma unroll
        for (int nt = 0; nt < 4; nt++) {
            int col = n0 + wn * 32 + nt * 8 + (l & 3) * 2;
            if (col >= Nvalid) continue;
            float2 bv = *reinterpret_cast<const float2*>(bias + col);
#pragma unroll
            for (int half = 0; half < 2; half++) {
                int row = m0 + wm * 32 + mt * 16 + (l >> 2) + half * 8;
                float v0 = acc[mt][nt][half * 2]     + bv.x;
                float v1 = acc[mt][nt][half * 2 + 1] + bv.y;
                if (EPI == EP_RESID) {
                    float2 r = *reinterpret_cast<const float2*>(Res + (size_t)row * ldc + col);
                    v0 += r.x; v1 += r.y;
                }
                if (EPI == EP_GELU) {
                    v0 = gelu_exact(v0);
                    v1 = gelu_exact(v1);
                    *reinterpret_cast<__half2*>(OutH + (size_t)row * ldc + col) =
                        __floats2half2_rn(v0, v1);
                } else if (EPI == EP_VALUE) {
                    int n = row / LQ, li = row - n * LQ;
                    int h = col >> 5, d = col & 31;
                    *reinterpret_cast<float2*>(Cout +
                        ((size_t)((n * NHEADS + h) * LQ + li)) * DH + d) = make_float2(v0, v1);
                } else {
                    *reinterpret_cast<float2*>(Cout + (size_t)row * ldc + col) = make_float2(v0, v1);
                }
            }
        }
    }
}

// ================= softmax over P=25: one warp per (token, head) ============
__global__ void __launch_bounds__(256) softmax_kernel(float* __restrict__ aw)
{
    int warp = threadIdx.x >> 5, lane = threadIdx.x & 31;
    size_t row = (size_t)blockIdx.x * 8 + warp;
    float* p = aw + row * NPTS;
    float v = (lane < NPTS) ? p[lane] : -1e30f;
    float mx = v;
#pragma unroll
    for (int o = 16; o > 0; o >>= 1) mx = fmaxf(mx, __shfl_xor_sync(0xffffffffu, mx, o));
    float e = (lane < NPTS) ? expf(v - mx) : 0.0f;
    float s = e;
#pragma unroll
    for (int o = 16; o > 0; o >>= 1) s += __shfl_xor_sync(0xffffffffu, s, o);
    if (lane < NPTS) p[lane] = e / s;
}

// ================= deformable sampling: warp per (token, head), lane = d ====
__global__ void __launch_bounds__(256) sample_kernel(const float* __restrict__ refp)
{
    int warpId = blockIdx.x * 8 + (threadIdx.x >> 5);
    int lane = threadIdx.x & 31;
    int token = warpId >> 3;
    int h = warpId & 7;
    int n = token / LQ;
    float rx = __ldg(refp + (size_t)token * 2);
    float ry = __ldg(refp + (size_t)token * 2 + 1);
    const float* offp = g_off + (size_t)token * (NHEADS * NPTS * 2) + h * (NPTS * 2);
    const float* awp  = g_aw  + (size_t)token * (NHEADS * NPTS)     + h * NPTS;
    const float* vb   = g_val + ((size_t)(n * NHEADS + h) * LQ) * DH + lane;
    float acc = 0.0f;
    for (int p = 0; p < NPTS; p++) {
        float ox = __ldg(offp + 2 * p);
        float oy = __ldg(offp + 2 * p + 1);
        float a  = __ldg(awp + p);
        float gx = fmaf(rx, (float)WDIM, ox) - 0.5f;
        float gy = fmaf(ry, (float)HDIM, oy) - 0.5f;
        float fx0 = floorf(gx), fy0 = floorf(gy);
        float fx = gx - fx0, fy = gy - fy0;
        int x0 = (int)fx0, y0 = (int)fy0;
        float w00 = (1.f - fx) * (1.f - fy) * a;
        float w10 = fx * (1.f - fy) * a;
        float w01 = (1.f - fx) * fy * a;
        float w11 = fx * fy * a;
        bool xv0 = (x0 >= 0) && (x0 < WDIM);
        bool xv1 = (x0 + 1 >= 0) && (x0 + 1 < WDIM);
        bool yv0 = (y0 >= 0) && (y0 < HDIM);
        bool yv1 = (y0 + 1 >= 0) && (y0 + 1 < HDIM);
        if (xv0 && yv0) acc = fmaf(w00, vb[(size_t)(y0 * WDIM + x0) * DH], acc);
        if (xv1 && yv0) acc = fmaf(w10, vb[(size_t)(y0 * WDIM + x0 + 1) * DH], acc);
        if (xv0 && yv1) acc = fmaf(w01, vb[(size_t)((y0 + 1) * WDIM + x0) * DH], acc);
        if (xv1 && yv1) acc = fmaf(w11, vb[(size_t)((y0 + 1) * WDIM + x0 + 1) * DH], acc);
    }
    g_at[(size_t)token * CDIM + h * DH + lane] = __float2half(acc);
}

// ================= launch =================
extern "C" void kernel_launch(void* const* d_in, const int* in_sizes, int n_in,
                              void* d_out, int out_size)
{
    (void)in_sizes; (void)n_in; (void)out_size;
    const float* x      = (const float*)d_in[0];
    const float* refp   = (const float*)d_in[1];
    const float* ln1g   = (const float*)d_in[4];
    const float* ln1b   = (const float*)d_in[5];
    const float* w_off  = (const float*)d_in[6];
    const float* b_off  = (const float*)d_in[7];
    const float* w_attn = (const float*)d_in[8];
    const float* b_attn = (const float*)d_in[9];
    const float* w_val  = (const float*)d_in[10];
    const float* b_val  = (const float*)d_in[11];
    const float* w_out  = (const float*)d_in[12];
    const float* b_out  = (const float*)d_in[13];
    const float* ln2g   = (const float*)d_in[14];
    const float* ln2b   = (const float*)d_in[15];
    const float* w_fc1  = (const float*)d_in[16];
    const float* b_fc1  = (const float*)d_in[17];
    const float* w_fc2  = (const float*)d_in[18];
    const float* b_fc2  = (const float*)d_in[19];
    float* out = (float*)d_out;

    __half *q, *at, *q2, *h1;
    __half *wvhi, *wvlo, *wohi, *wolo, *wahi, *walo, *wuhi, *wulo, *w1hi, *w1lo, *w2hi, *w2lo;
    float *pval, *poff, *paw, *px1;
    cudaGetSymbolAddress((void**)&q,  g_q);   cudaGetSymbolAddress((void**)&at, g_at);
    cudaGetSymbolAddress((void**)&q2, g_q2);  cudaGetSymbolAddress((void**)&h1, g_h1);
    cudaGetSymbolAddress((void**)&wvhi, g_wvhi); cudaGetSymbolAddress((void**)&wvlo, g_wvlo);
    cudaGetSymbolAddress((void**)&wohi, g_wohi); cudaGetSymbolAddress((void**)&wolo, g_wolo);
    cudaGetSymbolAddress((void**)&wahi, g_wahi); cudaGetSymbolAddress((void**)&walo, g_walo);
    cudaGetSymbolAddress((void**)&wuhi, g_wuhi); cudaGetSymbolAddress((void**)&wulo, g_wulo);
    cudaGetSymbolAddress((void**)&w1hi, g_w1hi); cudaGetSymbolAddress((void**)&w1lo, g_w1lo);
    cudaGetSymbolAddress((void**)&w2hi, g_w2hi); cudaGetSymbolAddress((void**)&w2lo, g_w2lo);
    cudaGetSymbolAddress((void**)&pval, g_val);
    cudaGetSymbolAddress((void**)&poff, g_off);
    cudaGetSymbolAddress((void**)&paw,  g_aw);
    cudaGetSymbolAddress((void**)&px1,  g_x1);

    const int SM_TOT = 2 * STAGE_BYTES;   // 64KB
    cudaFuncSetAttribute(mm_mma<EP_VALUE>, cudaFuncAttributeMaxDynamicSharedMemorySize, SM_TOT);
    cudaFuncSetAttribute(mm_mma<EP_PLAIN>, cudaFuncAttributeMaxDynamicSharedMemorySize, SM_TOT);
    cudaFuncSetAttribute(mm_mma<EP_RESID>, cudaFuncAttributeMaxDynamicSharedMemorySize, SM_TOT);
    cudaFuncSetAttribute(mm_mma<EP_GELU>,  cudaFuncAttributeMaxDynamicSharedMemorySize, SM_TOT);

    dim3 blk(256);
    dim3 wblk(32, 8);
    const int MT = NLTOK / 128;   // 144

    // Ordered so ncu's "-s 5" capture lands on mm_mma<EP_VALUE> (launch idx 5).
    wprep_kernel<<<dim3(8,  8),  wblk>>>(w_val,  wvhi, wvlo, 256,  256);   // 0
    wprep_kernel<<<dim3(8,  16), wblk>>>(w_off,  wohi, wolo, 256,  400);   // 1
    wprep_kernel<<<dim3(8,  8),  wblk>>>(w_attn, wahi, walo, 256,  200);   // 2
    wprep_kernel<<<dim3(8,  8),  wblk>>>(w_out,  wuhi, wulo, 256,  256);   // 3
    ln_kernel<<<NLTOK / 8, blk>>>(x, ln1g, ln1b, q);                       // 4
    mm_mma<EP_VALUE><<<dim3(4, MT), blk, SM_TOT>>>(q, wvhi, wvlo, b_val,   // 5 (profiled)
                                                   pval, nullptr, nullptr, 256, 256, 256);
    wprep_kernel<<<dim3(8,  32), wblk>>>(w_fc1,  w1hi, w1lo, 256,  1024);  // 6
    wprep_kernel<<<dim3(32, 8),  wblk>>>(w_fc2,  w2hi, w2lo, 1024, 256);   // 7
    mm_mma<EP_PLAIN><<<dim3(7, MT), blk, SM_TOT>>>(q, wohi, wolo, b_off,
                                                   poff, nullptr, nullptr, 256, 400, 400);
    mm_mma<EP_PLAIN><<<dim3(4, MT), blk, SM_TOT>>>(q, wahi, walo, b_attn,
                                                   paw, nullptr, nullptr, 256, 200, 200);
    softmax_kernel<<<(NLTOK * NHEADS) / 8, blk>>>(paw);
    sample_kernel<<<(NLTOK * NHEADS) / 8, blk>>>(refp);
    mm_mma<EP_RESID><<<dim3(4, MT), blk, SM_TOT>>>(at, wuhi, wulo, b_out,
                                                   px1, x, nullptr, 256, 256, 256);
    ln_kernel<<<NLTOK / 8, blk>>>(px1, ln2g, ln2b, q2);
    mm_mma<EP_GELU><<<dim3(16, MT), blk, SM_TOT>>>(q2, w1hi, w1lo, b_fc1,
                                                   nullptr, nullptr, h1, 256, 1024, 1024);
    mm_mma<EP_RESID><<<dim3(4, MT), blk, SM_TOT>>>(h1, w2hi, w2lo, b_fc2,
                                                   out, px1, nullptr, 1024, 256, 256);
}

// round 6
// speedup vs baseline: 2.5503x; 1.0971x over previous
#include <cuda_runtime.h>
#include <cuda_fp16.h>
#include <cstdint>
#include <math.h>

// Problem constants
#define NBATCH 2
#define HDIM   96
#define WDIM   96
#define CDIM   256
#define NHEADS 8
#define NPTS   25
#define DH     32
#define HIDDIM 1024
#define LQ     (HDIM*WDIM)      // 9216
#define NLTOK  (NBATCH*LQ)      // 18432

// ================= scratch (device globals, no allocation) =================
__device__ __align__(16) __half g_q  [NLTOK*CDIM];      // LN1 out, fp16
__device__ __align__(16) __half g_at [NLTOK*CDIM];      // attention out, fp16
__device__ __align__(16) __half g_q2 [NLTOK*CDIM];      // LN2 out, fp16
__device__ __align__(16) __half g_h1 [NLTOK*HIDDIM];    // gelu(fc1), fp16
__device__ __align__(16) float g_val [NLTOK*CDIM];      // [n,h,l,d]
__device__ __align__(16) float g_off [NLTOK*NHEADS*NPTS*2];
__device__ __align__(16) float g_aw  [NLTOK*NHEADS*NPTS];  // logits
__device__ __align__(16) float g_x1  [NLTOK*CDIM];
// transposed + padded weights: [Npad][K] fp16
__device__ __align__(16) __half g_wv [256*256];
__device__ __align__(16) __half g_wo [512*256];
__device__ __align__(16) __half g_wa [256*256];
__device__ __align__(16) __half g_wu [256*256];
__device__ __align__(16) __half g_w1 [1024*256];
__device__ __align__(16) __half g_w2 [256*1024];

// ================= low-level helpers (arch-agnostic PTX only) ==============
__device__ __forceinline__ uint32_t smem_u32(const void* p) {
    uint32_t a;
    asm("{ .reg .u64 t; cvta.to.shared.u64 t, %1; cvt.u32.u64 %0, t; }" : "=r"(a) : "l"(p));
    return a;
}
__device__ __forceinline__ void cp16(uint32_t s, const void* g) {
    asm volatile("cp.async.cg.shared.global [%0], [%1], 16;" :: "r"(s), "l"(g));
}
#define CP_COMMIT() asm volatile("cp.async.commit_group;" ::: "memory")
#define CP_WAIT(n)  asm volatile("cp.async.wait_group %0;" :: "n"(n) : "memory")

__device__ __forceinline__ void ldm4(uint32_t* r, uint32_t addr) {
    asm volatile("ldmatrix.sync.aligned.m8n8.x4.shared.b16 {%0,%1,%2,%3}, [%4];"
                 : "=r"(r[0]), "=r"(r[1]), "=r"(r[2]), "=r"(r[3]) : "r"(addr));
}
__device__ __forceinline__ void mma_f16(float* d, const uint32_t* a, const uint32_t* b) {
    asm volatile("mma.sync.aligned.m16n8k16.row.col.f32.f16.f16.f32 "
                 "{%0,%1,%2,%3}, {%4,%5,%6,%7}, {%8,%9}, {%0,%1,%2,%3};"
                 : "+f"(d[0]), "+f"(d[1]), "+f"(d[2]), "+f"(d[3])
                 : "r"(a[0]), "r"(a[1]), "r"(a[2]), "r"(a[3]), "r"(b[0]), "r"(b[1]));
}

// ================= weight prep: W[K,N] -> Wt[Npad][K], coalesced ============
__global__ void __launch_bounds__(256) wprep_kernel(const float* __restrict__ W,
                                                    __half* __restrict__ Wt,
                                                    int K, int N)
{
    __shared__ float s[32][33];
    int tx = threadIdx.x, ty = threadIdx.y;          // (32, 8)
    int k0 = blockIdx.x * 32, n0 = blockIdx.y * 32;
#pragma unroll
    for (int j = ty; j < 32; j += 8) {
        int n = n0 + tx;
        s[j][tx] = (n < N) ? W[(size_t)(k0 + j) * N + n] : 0.0f;
    }
    __syncthreads();
#pragma unroll
    for (int j = ty; j < 32; j += 8)
        Wt[(size_t)(n0 + j) * K + k0 + tx] = __float2half(s[tx][j]);
}

// ================= LayerNorm: warp/token, fp16 out ==========================
__global__ void __launch_bounds__(256) ln_kernel(const float* __restrict__ x,
                                                 const float* __restrict__ gam,
                                                 const float* __restrict__ bet,
                                                 __half* __restrict__ o)
{
    int warp = threadIdx.x >> 5, lane = threadIdx.x & 31;
    int token = blockIdx.x * 8 + warp;
    const float4* x4 = reinterpret_cast<const float4*>(x) + (size_t)token * 64;
    float4 v0 = x4[lane * 2];
    float4 v1 = x4[lane * 2 + 1];
    float s  = v0.x + v0.y + v0.z + v0.w + v1.x + v1.y + v1.z + v1.w;
    float sq = v0.x*v0.x + v0.y*v0.y + v0.z*v0.z + v0.w*v0.w
             + v1.x*v1.x + v1.y*v1.y + v1.z*v1.z + v1.w*v1.w;
#pragma unroll
    for (int of = 16; of > 0; of >>= 1) {
        s  += __shfl_xor_sync(0xffffffffu, s,  of);
        sq += __shfl_xor_sync(0xffffffffu, sq, of);
    }
    float mean = s * (1.0f / CDIM);
    float var  = sq * (1.0f / CDIM) - mean * mean;
    float rstd = rsqrtf(var + 1e-5f);
    const float4* g4 = reinterpret_cast<const float4*>(gam);
    const float4* b4 = reinterpret_cast<const float4*>(bet);
    float r[8];
    {
        float4 ga = g4[lane * 2],     ba = b4[lane * 2];
        float4 gb = g4[lane * 2 + 1], bb = b4[lane * 2 + 1];
        r[0] = (v0.x - mean) * rstd * ga.x + ba.x;
        r[1] = (v0.y - mean) * rstd * ga.y + ba.y;
        r[2] = (v0.z - mean) * rstd * ga.z + ba.z;
        r[3] = (v0.w - mean) * rstd * ga.w + ba.w;
        r[4] = (v1.x - mean) * rstd * gb.x + bb.x;
        r[5] = (v1.y - mean) * rstd * gb.y + bb.y;
        r[6] = (v1.z - mean) * rstd * gb.z + bb.z;
        r[7] = (v1.w - mean) * rstd * gb.w + bb.w;
    }
    size_t base = (size_t)token * CDIM + lane * 8;
#pragma unroll
    for (int i = 0; i < 8; i += 2)
        *reinterpret_cast<__half2*>(o + base + i) =
            __floats2half2_rn(r[i], r[i + 1]);
}

// ================= warp-MMA GEMM (single fp16) ==============================
// D[M,N] = A[M,K] @ B[N,K]^T, fp32 acc.
// BM=128, BN=64, BK=64, 256 thr (8 warps, 4x2 m-n), 2-stage cp.async.
// smem/stage: A 128x128B = 16KB; B 64x128B = 8KB.
enum { EP_VALUE = 0, EP_PLAIN = 1, EP_RESID = 2, EP_GELU = 3 };

__device__ __forceinline__ float gelu_exact(float v) {
    return 0.5f * v * (1.0f + erff(v * 0.70710678118654752f));
}

#define STAGE_BYTES 24576
#define B_OFF       16384

template <int EPI>
__global__ void __launch_bounds__(256) mm_mma(const __half* __restrict__ A,
                                              const __half* __restrict__ B,
                                              const float* __restrict__ bias,
                                              float* __restrict__ Cout,
                                              const float* __restrict__ Res,
                                              __half* __restrict__ OutH,
                                              int K, int Nvalid, int ldc)
{
    extern __shared__ __align__(128) char smem[];
    const uint32_t sb = smem_u32(smem);
    const int tid = threadIdx.x;
    const int wid = tid >> 5, l = tid & 31;
    const int wm = wid & 3, wn = wid >> 2;
    const int m0 = blockIdx.y * 128, n0 = blockIdx.x * 64;

    float acc[2][4][4];
#pragma unroll
    for (int i = 0; i < 2; i++)
#pragma unroll
        for (int j = 0; j < 4; j++)
#pragma unroll
            for (int q = 0; q < 4; q++) acc[i][j][q] = 0.0f;

    const int KC = K >> 6;

    auto load_stage = [&](int kcidx) {
        int k0 = kcidx << 6;
        uint32_t st = sb + (kcidx & 1) * STAGE_BYTES;
#pragma unroll
        for (int i = 0; i < 4; i++) {          // A: 1024 16B-chunks
            int id = tid + i * 256;
            int r = id >> 3, c = id & 7;
            cp16(st + r * 128 + ((c ^ (r & 7)) << 4),
                 A + (size_t)(m0 + r) * K + k0 + c * 8);
        }
#pragma unroll
        for (int i = 0; i < 2; i++) {          // B: 512 chunks
            int id = tid + i * 256;
            int r = id >> 3, c = id & 7;
            cp16(st + B_OFF + r * 128 + ((c ^ (r & 7)) << 4),
                 B + (size_t)(n0 + r) * K + k0 + c * 8);
        }
        CP_COMMIT();
    };

    load_stage(0);

    const int rowA = wm * 32 + (l & 15);
    const int cxA  = l >> 4;
    const int rowB = wn * 32 + (l & 7) + ((l >> 4) << 3);
    const int cxB  = (l >> 3) & 1;

    for (int kc = 0; kc < KC; kc++) {
        if (kc + 1 < KC) {
            load_stage(kc + 1);
            CP_WAIT(1);
        } else {
            CP_WAIT(0);
        }
        __syncthreads();

        uint32_t ab = sb + (kc & 1) * STAGE_BYTES;
        uint32_t bb = ab + B_OFF;
#pragma unroll
        for (int ks = 0; ks < 4; ks++) {
            uint32_t a[2][4], b[2][4];
#pragma unroll
            for (int mt = 0; mt < 2; mt++) {
                int row = rowA + mt * 16;
                ldm4(a[mt], ab + row * 128 + (((ks * 2 + cxA) ^ (row & 7)) << 4));
            }
#pragma unroll
            for (int ntp = 0; ntp < 2; ntp++) {
                int row = rowB + ntp * 16;
                ldm4(b[ntp], bb + row * 128 + (((ks * 2 + cxB) ^ (row & 7)) << 4));
            }
#pragma unroll
            for (int mt = 0; mt < 2; mt++)
#pragma unroll
                for (int nt = 0; nt < 4; nt++)
                    mma_f16(acc[mt][nt], a[mt], &b[nt >> 1][(nt & 1) * 2]);
        }
        __syncthreads();
    }

    // ---- epilogue ----
#pragma unroll
    for (int mt = 0; mt < 2; mt++) {
#pragma unroll
        for (int nt = 0; nt < 4; nt++) {
            int col = n0 + wn * 32 + nt * 8 + (l & 3) * 2;
            if (col >= Nvalid) continue;
            float2 bv = *reinterpret_cast<const float2*>(bias + col);
#pragma unroll
            for (int half = 0; half < 2; half++) {
                int row = m0 + wm * 32 + mt * 16 + (l >> 2) + half * 8;
                float v0 = acc[mt][nt][half * 2]     + bv.x;
                float v1 = acc[mt][nt][half * 2 + 1] + bv.y;
                if (EPI == EP_RESID) {
                    float2 r = *reinterpret_cast<const float2*>(Res + (size_t)row * ldc + col);
                    v0 += r.x; v1 += r.y;
                }
                if (EPI == EP_GELU) {
                    v0 = gelu_exact(v0);
                    v1 = gelu_exact(v1);
                    *reinterpret_cast<__half2*>(OutH + (size_t)row * ldc + col) =
                        __floats2half2_rn(v0, v1);
                } else if (EPI == EP_VALUE) {
                    int n = row / LQ, li = row - n * LQ;
                    int h = col >> 5, d = col & 31;
                    *reinterpret_cast<float2*>(Cout +
                        ((size_t)((n * NHEADS + h) * LQ + li)) * DH + d) = make_float2(v0, v1);
                } else {
                    *reinterpret_cast<float2*>(Cout + (size_t)row * ldc + col) = make_float2(v0, v1);
                }
            }
        }
    }
}

// ======== deformable sampling + fused softmax: warp per (token, head) =======
__global__ void __launch_bounds__(256) sample_kernel(const float* __restrict__ refp)
{
    int warpId = blockIdx.x * 8 + (threadIdx.x >> 5);
    int lane = threadIdx.x & 31;
    int token = warpId >> 3;
    int h = warpId & 7;
    int n = token / LQ;

    // in-warp softmax over the 25 logits of this (token, head)
    const float* awp = g_aw + (size_t)token * (NHEADS * NPTS) + h * NPTS;
    float logit = (lane < NPTS) ? __ldg(awp + lane) : -1e30f;
    float mx = logit;
#pragma unroll
    for (int o = 16; o > 0; o >>= 1) mx = fmaxf(mx, __shfl_xor_sync(0xffffffffu, mx, o));
    float e = (lane < NPTS) ? expf(logit - mx) : 0.0f;
    float ssum = e;
#pragma unroll
    for (int o = 16; o > 0; o >>= 1) ssum += __shfl_xor_sync(0xffffffffu, ssum, o);
    float myw = e / ssum;                    // lane p holds softmax weight p

    float rx = __ldg(refp + (size_t)token * 2);
    float ry = __ldg(refp + (size_t)token * 2 + 1);
    const float* offp = g_off + (size_t)token * (NHEADS * NPTS * 2) + h * (NPTS * 2);
    const float* vb   = g_val + ((size_t)(n * NHEADS + h) * LQ) * DH + lane;
    float acc = 0.0f;
    for (int p = 0; p < NPTS; p++) {
        float ox = __ldg(offp + 2 * p);
        float oy = __ldg(offp + 2 * p + 1);
        float a  = __shfl_sync(0xffffffffu, myw, p);
        float gx = fmaf(rx, (float)WDIM, ox) - 0.5f;
        float gy = fmaf(ry, (float)HDIM, oy) - 0.5f;
        float fx0 = floorf(gx), fy0 = floorf(gy);
        float fx = gx - fx0, fy = gy - fy0;
        int x0 = (int)fx0, y0 = (int)fy0;
        float w00 = (1.f - fx) * (1.f - fy) * a;
        float w10 = fx * (1.f - fy) * a;
        float w01 = (1.f - fx) * fy * a;
        float w11 = fx * fy * a;
        bool xv0 = (x0 >= 0) && (x0 < WDIM);
        bool xv1 = (x0 + 1 >= 0) && (x0 + 1 < WDIM);
        bool yv0 = (y0 >= 0) && (y0 < HDIM);
        bool yv1 = (y0 + 1 >= 0) && (y0 + 1 < HDIM);
        if (xv0 && yv0) acc = fmaf(w00, vb[(size_t)(y0 * WDIM + x0) * DH], acc);
        if (xv1 && yv0) acc = fmaf(w10, vb[(size_t)(y0 * WDIM + x0 + 1) * DH], acc);
        if (xv0 && yv1) acc = fmaf(w01, vb[(size_t)((y0 + 1) * WDIM + x0) * DH], acc);
        if (xv1 && yv1) acc = fmaf(w11, vb[(size_t)((y0 + 1) * WDIM + x0 + 1) * DH], acc);
    }
    g_at[(size_t)token * CDIM + h * DH + lane] = __float2half(acc);
}

// ================= launch =================
extern "C" void kernel_launch(void* const* d_in, const int* in_sizes, int n_in,
                              void* d_out, int out_size)
{
    (void)in_sizes; (void)n_in; (void)out_size;
    const float* x      = (const float*)d_in[0];
    const float* refp   = (const float*)d_in[1];
    const float* ln1g   = (const float*)d_in[4];
    const float* ln1b   = (const float*)d_in[5];
    const float* w_off  = (const float*)d_in[6];
    const float* b_off  = (const float*)d_in[7];
    const float* w_attn = (const float*)d_in[8];
    const float* b_attn = (const float*)d_in[9];
    const float* w_val  = (const float*)d_in[10];
    const float* b_val  = (const float*)d_in[11];
    const float* w_out  = (const float*)d_in[12];
    const float* b_out  = (const float*)d_in[13];
    const float* ln2g   = (const float*)d_in[14];
    const float* ln2b   = (const float*)d_in[15];
    const float* w_fc1  = (const float*)d_in[16];
    const float* b_fc1  = (const float*)d_in[17];
    const float* w_fc2  = (const float*)d_in[18];
    const float* b_fc2  = (const float*)d_in[19];
    float* out = (float*)d_out;

    __half *q, *at, *q2, *h1, *wv, *wo, *wa, *wu, *w1, *w2;
    float *pval, *poff, *paw, *px1;
    cudaGetSymbolAddress((void**)&q,  g_q);   cudaGetSymbolAddress((void**)&at, g_at);
    cudaGetSymbolAddress((void**)&q2, g_q2);  cudaGetSymbolAddress((void**)&h1, g_h1);
    cudaGetSymbolAddress((void**)&wv, g_wv);  cudaGetSymbolAddress((void**)&wo, g_wo);
    cudaGetSymbolAddress((void**)&wa, g_wa);  cudaGetSymbolAddress((void**)&wu, g_wu);
    cudaGetSymbolAddress((void**)&w1, g_w1);  cudaGetSymbolAddress((void**)&w2, g_w2);
    cudaGetSymbolAddress((void**)&pval, g_val);
    cudaGetSymbolAddress((void**)&poff, g_off);
    cudaGetSymbolAddress((void**)&paw,  g_aw);
    cudaGetSymbolAddress((void**)&px1,  g_x1);

    const int SM_TOT = 2 * STAGE_BYTES;   // 48KB
    cudaFuncSetAttribute(mm_mma<EP_VALUE>, cudaFuncAttributeMaxDynamicSharedMemorySize, SM_TOT);
    cudaFuncSetAttribute(mm_mma<EP_PLAIN>, cudaFuncAttributeMaxDynamicSharedMemorySize, SM_TOT);
    cudaFuncSetAttribute(mm_mma<EP_RESID>, cudaFuncAttributeMaxDynamicSharedMemorySize, SM_TOT);
    cudaFuncSetAttribute(mm_mma<EP_GELU>,  cudaFuncAttributeMaxDynamicSharedMemorySize, SM_TOT);

    dim3 blk(256);
    dim3 wblk(32, 8);
    const int MT = NLTOK / 128;   // 144

    wprep_kernel<<<dim3(8,  8),  wblk>>>(w_val,  wv, 256,  256);
    wprep_kernel<<<dim3(8,  16), wblk>>>(w_off,  wo, 256,  400);
    wprep_kernel<<<dim3(8,  8),  wblk>>>(w_attn, wa, 256,  200);
    wprep_kernel<<<dim3(8,  8),  wblk>>>(w_out,  wu, 256,  256);
    wprep_kernel<<<dim3(8,  32), wblk>>>(w_fc1,  w1, 256,  1024);
    wprep_kernel<<<dim3(32, 8),  wblk>>>(w_fc2,  w2, 1024, 256);

    ln_kernel<<<NLTOK / 8, blk>>>(x, ln1g, ln1b, q);
    mm_mma<EP_VALUE><<<dim3(4, MT), blk, SM_TOT>>>(q, wv, b_val,
                                                   pval, nullptr, nullptr, 256, 256, 256);
    mm_mma<EP_PLAIN><<<dim3(7, MT), blk, SM_TOT>>>(q, wo, b_off,
                                                   poff, nullptr, nullptr, 256, 400, 400);
    mm_mma<EP_PLAIN><<<dim3(4, MT), blk, SM_TOT>>>(q, wa, b_attn,
                                                   paw, nullptr, nullptr, 256, 200, 200);
    sample_kernel<<<(NLTOK * NHEADS) / 8, blk>>>(refp);
    mm_mma<EP_RESID><<<dim3(4, MT), blk, SM_TOT>>>(at, wu, b_out,
                                                   px1, x, nullptr, 256, 256, 256);
    ln_kernel<<<NLTOK / 8, blk>>>(px1, ln2g, ln2b, q2);
    mm_mma<EP_GELU><<<dim3(16, MT), blk, SM_TOT>>>(q2, w1, b_fc1,
                                                   nullptr, nullptr, h1, 256, 1024, 1024);
    mm_mma<EP_RESID><<<dim3(4, MT), blk, SM_TOT>>>(h1, w2, b_fc2,
                                                   out, px1, nullptr, 1024, 256, 256);
}

// round 8
// speedup vs baseline: 2.7330x; 1.0717x over previous
#include <cuda_runtime.h>
#include <cuda_fp16.h>
#include <cstdint>
#include <math.h>

// Problem constants
#define NBATCH 2
#define HDIM   96
#define WDIM   96
#define CDIM   256
#define NHEADS 8
#define NPTS   25
#define DH     32
#define HIDDIM 1024
#define LQ     (HDIM*WDIM)      // 9216
#define NLTOK  (NBATCH*LQ)      // 18432
#define NQKV   896              // padded 256(val)+400(off)+200(attn)
#define OA_LD  600              // combined off(400)+attn(200) row stride

// ================= scratch (device globals, no allocation) =================
__device__ __align__(16) __half g_q  [NLTOK*CDIM];      // LN1 out
__device__ __align__(16) __half g_at [NLTOK*CDIM];      // attention out
__device__ __align__(16) __half g_q2 [NLTOK*CDIM];      // LN2 out
__device__ __align__(16) __half g_h1 [NLTOK*HIDDIM];    // gelu(fc1)
__device__ __align__(16) __half g_val[NLTOK*CDIM];      // value [n,h,l,d], fp16
__device__ __align__(16) float  g_oa [NLTOK*OA_LD];     // offsets(400) + logits(200)
__device__ __align__(16) float  g_x1 [NLTOK*CDIM];
// transposed + padded weights [Npad][K] fp16
__device__ __align__(16) __half g_wq [NQKV*256];        // val|off|attn stacked
__device__ __align__(16) __half g_wu [256*256];
__device__ __align__(16) __half g_w1 [1024*256];
__device__ __align__(16) __half g_w2 [256*1024];

// ================= low-level helpers ==================
__device__ __forceinline__ uint32_t smem_u32(const void* p) {
    uint32_t a;
    asm("{ .reg .u64 t; cvta.to.shared.u64 t, %1; cvt.u32.u64 %0, t; }" : "=r"(a) : "l"(p));
    return a;
}
__device__ __forceinline__ void cp16(uint32_t s, const void* g) {
    asm volatile("cp.async.cg.shared.global [%0], [%1], 16;" :: "r"(s), "l"(g));
}
#define CP_COMMIT() asm volatile("cp.async.commit_group;" ::: "memory")
#define CP_WAIT(n)  asm volatile("cp.async.wait_group %0;" :: "n"(n) : "memory")

__device__ __forceinline__ void ldm4(uint32_t* r, uint32_t addr) {
    asm volatile("ldmatrix.sync.aligned.m8n8.x4.shared.b16 {%0,%1,%2,%3}, [%4];"
                 : "=r"(r[0]), "=r"(r[1]), "=r"(r[2]), "=r"(r[3]) : "r"(addr));
}
__device__ __forceinline__ void mma_f16(float* d, const uint32_t* a, const uint32_t* b) {
    asm volatile("mma.sync.aligned.m16n8k16.row.col.f32.f16.f16.f32 "
                 "{%0,%1,%2,%3}, {%4,%5,%6,%7}, {%8,%9}, {%0,%1,%2,%3};"
                 : "+f"(d[0]), "+f"(d[1]), "+f"(d[2]), "+f"(d[3])
                 : "r"(a[0]), "r"(a[1]), "r"(a[2]), "r"(a[3]), "r"(b[0]), "r"(b[1]));
}

// ========== single mega weight-prep: all 6 jobs, block-range dispatch ========
// job: 32x32 transpose tiles, src W[K,N] col n -> dst Wt[row0+n][k]
__global__ void __launch_bounds__(256) wprep_all(const float* __restrict__ w_val,
                                                 const float* __restrict__ w_off,
                                                 const float* __restrict__ w_attn,
                                                 const float* __restrict__ w_out,
                                                 const float* __restrict__ w_fc1,
                                                 const float* __restrict__ w_fc2,
                                                 __half* __restrict__ wq,
                                                 __half* __restrict__ wu,
                                                 __half* __restrict__ w1,
                                                 __half* __restrict__ w2)
{
    int t = blockIdx.x;
    const float* src; __half* dst;
    int row0, K, N, Nallot, ktiles;
    if      (t < 64)  { src=w_val;  dst=wq; row0=0;   K=256;  N=256;  Nallot=256;  ktiles=8;  t -= 0; }
    else if (t < 168) { src=w_off;  dst=wq; row0=256; K=256;  N=400;  Nallot=400;  ktiles=8;  t -= 64; }
    else if (t < 232) { src=w_attn; dst=wq; row0=656; K=256;  N=200;  Nallot=240;  ktiles=8;  t -= 168; }
    else if (t < 296) { src=w_out;  dst=wu; row0=0;   K=256;  N=256;  Nallot=256;  ktiles=8;  t -= 232; }
    else if (t < 552) { src=w_fc1;  dst=w1; row0=0;   K=256;  N=1024; Nallot=1024; ktiles=8;  t -= 296; }
    else              { src=w_fc2;  dst=w2; row0=0;   K=1024; N=256;  Nallot=256;  ktiles=32; t -= 552; }
    int kt = t % ktiles, nt = t / ktiles;
    int k0 = kt * 32, n0 = nt * 32;

    __shared__ float s[32][33];
    int tx = threadIdx.x & 31, ty = threadIdx.x >> 5;   // (32, 8)
#pragma unroll
    for (int j = ty; j < 32; j += 8) {
        int n = n0 + tx;
        s[j][tx] = (n < N) ? src[(size_t)(k0 + j) * N + n] : 0.0f;
    }
    __syncthreads();
#pragma unroll
    for (int j = ty; j < 32; j += 8) {
        int n = n0 + j;
        if (n < Nallot)
            dst[(size_t)(row0 + n) * K + k0 + tx] = __float2half(s[tx][j]);
    }
}

// ================= LayerNorm: warp/token, fp16 out ==========================
__global__ void __launch_bounds__(256) ln_kernel(const float* __restrict__ x,
                                                 const float* __restrict__ gam,
                                                 const float* __restrict__ bet,
                                                 __half* __restrict__ o)
{
    int warp = threadIdx.x >> 5, lane = threadIdx.x & 31;
    int token = blockIdx.x * 8 + warp;
    const float4* x4 = reinterpret_cast<const float4*>(x) + (size_t)token * 64;
    float4 v0 = x4[lane * 2];
    float4 v1 = x4[lane * 2 + 1];
    float s  = v0.x + v0.y + v0.z + v0.w + v1.x + v1.y + v1.z + v1.w;
    float sq = v0.x*v0.x + v0.y*v0.y + v0.z*v0.z + v0.w*v0.w
             + v1.x*v1.x + v1.y*v1.y + v1.z*v1.z + v1.w*v1.w;
#pragma unroll
    for (int of = 16; of > 0; of >>= 1) {
        s  += __shfl_xor_sync(0xffffffffu, s,  of);
        sq += __shfl_xor_sync(0xffffffffu, sq, of);
    }
    float mean = s * (1.0f / CDIM);
    float var  = sq * (1.0f / CDIM) - mean * mean;
    float rstd = rsqrtf(var + 1e-5f);
    const float4* g4 = reinterpret_cast<const float4*>(gam);
    const float4* b4 = reinterpret_cast<const float4*>(bet);
    float r[8];
    {
        float4 ga = g4[lane * 2],     ba = b4[lane * 2];
        float4 gb = g4[lane * 2 + 1], bb = b4[lane * 2 + 1];
        r[0] = (v0.x - mean) * rstd * ga.x + ba.x;
        r[1] = (v0.y - mean) * rstd * ga.y + ba.y;
        r[2] = (v0.z - mean) * rstd * ga.z + ba.z;
        r[3] = (v0.w - mean) * rstd * ga.w + ba.w;
        r[4] = (v1.x - mean) * rstd * gb.x + bb.x;
        r[5] = (v1.y - mean) * rstd * gb.y + bb.y;
        r[6] = (v1.z - mean) * rstd * gb.z + bb.z;
        r[7] = (v1.w - mean) * rstd * gb.w + bb.w;
    }
    size_t base = (size_t)token * CDIM + lane * 8;
#pragma unroll
    for (int i = 0; i < 8; i += 2)
        *reinterpret_cast<__half2*>(o + base + i) =
            __floats2half2_rn(r[i], r[i + 1]);
}

// ================= warp-MMA GEMM ==============================
// BM=128, BN=64, BK=64, 256 thr, 2-stage cp.async.
enum { EP_QKV = 0, EP_RESID = 2, EP_GELU = 3 };

__device__ __forceinline__ float gelu_exact(float v) {
    return 0.5f * v * (1.0f + erff(v * 0.70710678118654752f));
}

#define STAGE_BYTES 24576
#define B_OFF       16384

template <int EPI>
__global__ void __launch_bounds__(256) mm_mma(const __half* __restrict__ A,
                                              const __half* __restrict__ B,
                                              const float* __restrict__ bias,
                                              float* __restrict__ Cout,
                                              const float* __restrict__ Res,
                                              __half* __restrict__ OutH,
                                              const float* __restrict__ b_off,
                                              const float* __restrict__ b_attn,
                                              float* __restrict__ OA,
                                              int K, int Nvalid, int ldc)
{
    extern __shared__ __align__(128) char smem[];
    const uint32_t sb = smem_u32(smem);
    const int tid = threadIdx.x;
    const int wid = tid >> 5, l = tid & 31;
    const int wm = wid & 3, wn = wid >> 2;
    const int m0 = blockIdx.y * 128, n0 = blockIdx.x * 64;

    float acc[2][4][4];
#pragma unroll
    for (int i = 0; i < 2; i++)
#pragma unroll
        for (int j = 0; j < 4; j++)
#pragma unroll
            for (int q = 0; q < 4; q++) acc[i][j][q] = 0.0f;

    const int KC = K >> 6;

    auto load_stage = [&](int kcidx) {
        int k0 = kcidx << 6;
        uint32_t st = sb + (kcidx & 1) * STAGE_BYTES;
#pragma unroll
        for (int i = 0; i < 4; i++) {
            int id = tid + i * 256;
            int r = id >> 3, c = id & 7;
            cp16(st + r * 128 + ((c ^ (r & 7)) << 4),
                 A + (size_t)(m0 + r) * K + k0 + c * 8);
        }
#pragma unroll
        for (int i = 0; i < 2; i++) {
            int id = tid + i * 256;
            int r = id >> 3, c = id & 7;
            cp16(st + B_OFF + r * 128 + ((c ^ (r & 7)) << 4),
                 B + (size_t)(n0 + r) * K + k0 + c * 8);
        }
        CP_COMMIT();
    };

    load_stage(0);

    const int rowA = wm * 32 + (l & 15);
    const int cxA  = l >> 4;
    const int rowB = wn * 32 + (l & 7) + ((l >> 4) << 3);
    const int cxB  = (l >> 3) & 1;

    for (int kc = 0; kc < KC; kc++) {
        if (kc + 1 < KC) {
            load_stage(kc + 1);
            CP_WAIT(1);
        } else {
            CP_WAIT(0);
        }
        __syncthreads();

        uint32_t ab = sb + (kc & 1) * STAGE_BYTES;
        uint32_t bb = ab + B_OFF;
#pragma unroll
        for (int ks = 0; ks < 4; ks++) {
            uint32_t a[2][4], b[2][4];
#pragma unroll
            for (int mt = 0; mt < 2; mt++) {
                int row = rowA + mt * 16;
                ldm4(a[mt], ab + row * 128 + (((ks * 2 + cxA) ^ (row & 7)) << 4));
            }
#pragma unroll
            for (int ntp = 0; ntp < 2; ntp++) {
                int row = rowB + ntp * 16;
                ldm4(b[ntp], bb + row * 128 + (((ks * 2 + cxB) ^ (row & 7)) << 4));
            }
#pragma unroll
            for (int mt = 0; mt < 2; mt++)
#pragma unroll
                for (int nt = 0; nt < 4; nt++)
                    mma_f16(acc[mt][nt], a[mt], &b[nt >> 1][(nt & 1) * 2]);
        }
        __syncthreads();
    }

    // ---- epilogue ----
#pragma unroll
    for (int mt = 0; mt < 2; mt++) {
#pragma unroll
        for (int nt = 0; nt < 4; nt++) {
            int col = n0 + wn * 32 + nt * 8 + (l & 3) * 2;
            if (col >= Nvalid) continue;
#pragma unroll
            for (int half = 0; half < 2; half++) {
                int row = m0 + wm * 32 + mt * 16 + (l >> 2) + half * 8;
                float v0 = acc[mt][nt][half * 2];
                float v1 = acc[mt][nt][half * 2 + 1];
                if (EPI == EP_QKV) {
                    if (col < 256) {           // value: scatter fp16 into [n,h,l,d]
                        float2 bv = *reinterpret_cast<const float2*>(bias + col);
                        v0 += bv.x; v1 += bv.y;
                        int n = row / LQ, li = row - n * LQ;
                        int h = col >> 5, d = col & 31;
                        *reinterpret_cast<__half2*>(OutH +
                            ((size_t)((n * NHEADS + h) * LQ + li)) * DH + d) =
                            __floats2half2_rn(v0, v1);
                    } else if (col < 656) {    // offsets
                        float2 bv = *reinterpret_cast<const float2*>(b_off + (col - 256));
                        v0 += bv.x; v1 += bv.y;
                        *reinterpret_cast<float2*>(OA + (size_t)row * OA_LD + (col - 256)) =
                            make_float2(v0, v1);
                    } else {                   // attn logits
                        float2 bv = *reinterpret_cast<const float2*>(b_attn + (col - 656));
                        v0 += bv.x; v1 += bv.y;
                        *reinterpret_cast<float2*>(OA + (size_t)row * OA_LD + 400 + (col - 656)) =
                            make_float2(v0, v1);
                    }
                } else {
                    float2 bv = *reinterpret_cast<const float2*>(bias + col);
                    v0 += bv.x; v1 += bv.y;
                    if (EPI == EP_RESID) {
                        float2 r = *reinterpret_cast<const float2*>(Res + (size_t)row * ldc + col);
                        v0 += r.x; v1 += r.y;
                        *reinterpret_cast<float2*>(Cout + (size_t)row * ldc + col) =
                            make_float2(v0, v1);
                    }
                    if (EPI == EP_GELU) {
                        v0 = gelu_exact(v0);
                        v1 = gelu_exact(v1);
                        *reinterpret_cast<__half2*>(OutH + (size_t)row * ldc + col) =
                            __floats2half2_rn(v0, v1);
                    }
                }
            }
        }
    }
}

// ======== deformable sampling + fused softmax: warp per (token, head) =======
__global__ void __launch_bounds__(256) sample_kernel(const float* __restrict__ refp)
{
    int warpId = blockIdx.x * 8 + (threadIdx.x >> 5);
    int lane = threadIdx.x & 31;
    int token = warpId >> 3;
    int h = warpId & 7;
    int n = token / LQ;

    const float* oa = g_oa + (size_t)token * OA_LD;
    // softmax over 25 logits
    float logit = (lane < NPTS) ? __ldg(oa + 400 + h * NPTS + lane) : -1e30f;
    float mx = logit;
#pragma unroll
    for (int o = 16; o > 0; o >>= 1) mx = fmaxf(mx, __shfl_xor_sync(0xffffffffu, mx, o));
    float e = (lane < NPTS) ? expf(logit - mx) : 0.0f;
    float ssum = e;
#pragma unroll
    for (int o = 16; o > 0; o >>= 1) ssum += __shfl_xor_sync(0xffffffffu, ssum, o);
    float myw = e / ssum;

    float rx = __ldg(refp + (size_t)token * 2);
    float ry = __ldg(refp + (size_t)token * 2 + 1);
    const float* offp = oa + h * (NPTS * 2);
    const __half* vb  = g_val + ((size_t)(n * NHEADS + h) * LQ) * DH + lane;
    float acc = 0.0f;
    for (int p = 0; p < NPTS; p++) {
        float ox = __ldg(offp + 2 * p);
        float oy = __ldg(offp + 2 * p + 1);
        float a  = __shfl_sync(0xffffffffu, myw, p);
        float gx = fmaf(rx, (float)WDIM, ox) - 0.5f;
        float gy = fmaf(ry, (float)HDIM, oy) - 0.5f;
        float fx0 = floorf(gx), fy0 = floorf(gy);
        float fx = gx - fx0, fy = gy - fy0;
        int x0 = (int)fx0, y0 = (int)fy0;
        float w00 = (1.f - fx) * (1.f - fy) * a;
        float w10 = fx * (1.f - fy) * a;
        float w01 = (1.f - fx) * fy * a;
        float w11 = fx * fy * a;
        bool xv0 = (x0 >= 0) && (x0 < WDIM);
        bool xv1 = (x0 + 1 >= 0) && (x0 + 1 < WDIM);
        bool yv0 = (y0 >= 0) && (y0 < HDIM);
        bool yv1 = (y0 + 1 >= 0) && (y0 + 1 < HDIM);
        if (xv0 && yv0) acc = fmaf(w00, __half2float(vb[(size_t)(y0 * WDIM + x0) * DH]), acc);
        if (xv1 && yv0) acc = fmaf(w10, __half2float(vb[(size_t)(y0 * WDIM + x0 + 1) * DH]), acc);
        if (xv0 && yv1) acc = fmaf(w01, __half2float(vb[(size_t)((y0 + 1) * WDIM + x0) * DH]), acc);
        if (xv1 && yv1) acc = fmaf(w11, __half2float(vb[(size_t)((y0 + 1) * WDIM + x0 + 1) * DH]), acc);
    }
    g_at[(size_t)token * CDIM + h * DH + lane] = __float2half(acc);
}

// ================= launch =================
extern "C" void kernel_launch(void* const* d_in, const int* in_sizes, int n_in,
                              void* d_out, int out_size)
{
    (void)in_sizes; (void)n_in; (void)out_size;
    const float* x      = (const float*)d_in[0];
    const float* refp   = (const float*)d_in[1];
    const float* ln1g   = (const float*)d_in[4];
    const float* ln1b   = (const float*)d_in[5];
    const float* w_off  = (const float*)d_in[6];
    const float* b_off  = (const float*)d_in[7];
    const float* w_attn = (const float*)d_in[8];
    const float* b_attn = (const float*)d_in[9];
    const float* w_val  = (const float*)d_in[10];
    const float* b_val  = (const float*)d_in[11];
    const float* w_out  = (const float*)d_in[12];
    const float* b_out  = (const float*)d_in[13];
    const float* ln2g   = (const float*)d_in[14];
    const float* ln2b   = (const float*)d_in[15];
    const float* w_fc1  = (const float*)d_in[16];
    const float* b_fc1  = (const float*)d_in[17];
    const float* w_fc2  = (const float*)d_in[18];
    const float* b_fc2  = (const float*)d_in[19];
    float* out = (float*)d_out;

    __half *q, *at, *q2, *h1, *wq, *wu, *w1, *w2, *pval;
    float *poa, *px1;
    cudaGetSymbolAddress((void**)&q,  g_q);   cudaGetSymbolAddress((void**)&at, g_at);
    cudaGetSymbolAddress((void**)&q2, g_q2);  cudaGetSymbolAddress((void**)&h1, g_h1);
    cudaGetSymbolAddress((void**)&wq, g_wq);  cudaGetSymbolAddress((void**)&wu, g_wu);
    cudaGetSymbolAddress((void**)&w1, g_w1);  cudaGetSymbolAddress((void**)&w2, g_w2);
    cudaGetSymbolAddress((void**)&pval, g_val);
    cudaGetSymbolAddress((void**)&poa,  g_oa);
    cudaGetSymbolAddress((void**)&px1,  g_x1);

    const int SM_TOT = 2 * STAGE_BYTES;   // 48KB
    cudaFuncSetAttribute(mm_mma<EP_QKV>,  cudaFuncAttributeMaxDynamicSharedMemorySize, SM_TOT);
    cudaFuncSetAttribute(mm_mma<EP_RESID>, cudaFuncAttributeMaxDynamicSharedMemorySize, SM_TOT);
    cudaFuncSetAttribute(mm_mma<EP_GELU>, cudaFuncAttributeMaxDynamicSharedMemorySize, SM_TOT);

    dim3 blk(256);
    const int MT = NLTOK / 128;   // 144

    wprep_all<<<808, blk>>>(w_val, w_off, w_attn, w_out, w_fc1, w_fc2, wq, wu, w1, w2);
    ln_kernel<<<NLTOK / 8, blk>>>(x, ln1g, ln1b, q);
    mm_mma<EP_QKV><<<dim3(14, MT), blk, SM_TOT>>>(q, wq, b_val, nullptr, nullptr, pval,
                                                  b_off, b_attn, poa, 256, 856, 0);
    sample_kernel<<<(NLTOK * NHEADS) / 8, blk>>>(refp);
    mm_mma<EP_RESID><<<dim3(4, MT), blk, SM_TOT>>>(at, wu, b_out, px1, x, nullptr,
                                                   nullptr, nullptr, nullptr, 256, 256, 256);
    ln_kernel<<<NLTOK / 8, blk>>>(px1, ln2g, ln2b, q2);
    mm_mma<EP_GELU><<<dim3(16, MT), blk, SM_TOT>>>(q2, w1, b_fc1, nullptr, nullptr, h1,
                                                   nullptr, nullptr, nullptr, 256, 1024, 1024);
    mm_mma<EP_RESID><<<dim3(4, MT), blk, SM_TOT>>>(h1, w2, b_fc2, out, px1, nullptr,
                                                   nullptr, nullptr, nullptr, 1024, 256, 256);
}

// round 10
// speedup vs baseline: 4.7996x; 1.7561x over previous
#include <cuda_runtime.h>
#include <cuda_fp16.h>
#include <cstdint>
#include <math.h>

// Problem constants
#define NBATCH 2
#define HDIM   96
#define WDIM   96
#define CDIM   256
#define NHEADS 8
#define NPTS   25
#define DH     32
#define HIDDIM 1024
#define LQ     (HDIM*WDIM)      // 9216
#define NLTOK  (NBATCH*LQ)      // 18432
#define NQKV   896
#define OA_LD  600              // combined off(400)+attn(200) row stride

// ================= scratch (device globals, no allocation) =================
__device__ __align__(16) __half g_q  [NLTOK*CDIM];
__device__ __align__(16) __half g_at [NLTOK*CDIM];
__device__ __align__(16) __half g_q2 [NLTOK*CDIM];
__device__ __align__(16) __half g_h1 [NLTOK*HIDDIM];
__device__ __align__(16) __half g_val[NLTOK*CDIM];      // value [n,h,l,d], fp16
__device__ __align__(16) float  g_oa [NLTOK*OA_LD];
__device__ __align__(16) float  g_x1 [NLTOK*CDIM];
__device__ __align__(16) __half g_wq [NQKV*256];
__device__ __align__(16) __half g_wu [256*256];
__device__ __align__(16) __half g_w1 [1024*256];
__device__ __align__(16) __half g_w2 [256*1024];

// ================= low-level helpers ==================
__device__ __forceinline__ uint32_t smem_u32(const void* p) {
    uint32_t a;
    asm("{ .reg .u64 t; cvta.to.shared.u64 t, %1; cvt.u32.u64 %0, t; }" : "=r"(a) : "l"(p));
    return a;
}
__device__ __forceinline__ void cp16(uint32_t s, const void* g) {
    asm volatile("cp.async.cg.shared.global [%0], [%1], 16;" :: "r"(s), "l"(g));
}
#define CP_COMMIT() asm volatile("cp.async.commit_group;" ::: "memory")
#define CP_WAIT(n)  asm volatile("cp.async.wait_group %0;" :: "n"(n) : "memory")

__device__ __forceinline__ void ldm4(uint32_t* r, uint32_t addr) {
    asm volatile("ldmatrix.sync.aligned.m8n8.x4.shared.b16 {%0,%1,%2,%3}, [%4];"
                 : "=r"(r[0]), "=r"(r[1]), "=r"(r[2]), "=r"(r[3]) : "r"(addr));
}
__device__ __forceinline__ void mma_f16(float* d, const uint32_t* a, const uint32_t* b) {
    asm volatile("mma.sync.aligned.m16n8k16.row.col.f32.f16.f16.f32 "
                 "{%0,%1,%2,%3}, {%4,%5,%6,%7}, {%8,%9}, {%0,%1,%2,%3};"
                 : "+f"(d[0]), "+f"(d[1]), "+f"(d[2]), "+f"(d[3])
                 : "r"(a[0]), "r"(a[1]), "r"(a[2]), "r"(a[3]), "r"(b[0]), "r"(b[1]));
}

// ========== single mega weight-prep ========
__global__ void __launch_bounds__(256) wprep_all(const float* __restrict__ w_val,
                                                 const float* __restrict__ w_off,
                                                 const float* __restrict__ w_attn,
                                                 const float* __restrict__ w_out,
                                                 const float* __restrict__ w_fc1,
                                                 const float* __restrict__ w_fc2,
                                                 __half* __restrict__ wq,
                                                 __half* __restrict__ wu,
                                                 __half* __restrict__ w1,
                                                 __half* __restrict__ w2)
{
    int t = blockIdx.x;
    const float* src; __half* dst;
    int row0, K, N, Nallot, ktiles;
    if      (t < 64)  { src=w_val;  dst=wq; row0=0;   K=256;  N=256;  Nallot=256;  ktiles=8;  t -= 0; }
    else if (t < 168) { src=w_off;  dst=wq; row0=256; K=256;  N=400;  Nallot=400;  ktiles=8;  t -= 64; }
    else if (t < 232) { src=w_attn; dst=wq; row0=656; K=256;  N=200;  Nallot=240;  ktiles=8;  t -= 168; }
    else if (t < 296) { src=w_out;  dst=wu; row0=0;   K=256;  N=256;  Nallot=256;  ktiles=8;  t -= 232; }
    else if (t < 552) { src=w_fc1;  dst=w1; row0=0;   K=256;  N=1024; Nallot=1024; ktiles=8;  t -= 296; }
    else              { src=w_fc2;  dst=w2; row0=0;   K=1024; N=256;  Nallot=256;  ktiles=32; t -= 552; }
    int kt = t % ktiles, nt = t / ktiles;
    int k0 = kt * 32, n0 = nt * 32;

    __shared__ float s[32][33];
    int tx = threadIdx.x & 31, ty = threadIdx.x >> 5;
#pragma unroll
    for (int j = ty; j < 32; j += 8) {
        int n = n0 + tx;
        s[j][tx] = (n < N) ? src[(size_t)(k0 + j) * N + n] : 0.0f;
    }
    __syncthreads();
#pragma unroll
    for (int j = ty; j < 32; j += 8) {
        int n = n0 + j;
        if (n < Nallot)
            dst[(size_t)(row0 + n) * K + k0 + tx] = __float2half(s[tx][j]);
    }
}

// ================= LayerNorm ==========================
__global__ void __launch_bounds__(256) ln_kernel(const float* __restrict__ x,
                                                 const float* __restrict__ gam,
                                                 const float* __restrict__ bet,
                                                 __half* __restrict__ o)
{
    int warp = threadIdx.x >> 5, lane = threadIdx.x & 31;
    int token = blockIdx.x * 8 + warp;
    const float4* x4 = reinterpret_cast<const float4*>(x) + (size_t)token * 64;
    float4 v0 = x4[lane * 2];
    float4 v1 = x4[lane * 2 + 1];
    float s  = v0.x + v0.y + v0.z + v0.w + v1.x + v1.y + v1.z + v1.w;
    float sq = v0.x*v0.x + v0.y*v0.y + v0.z*v0.z + v0.w*v0.w
             + v1.x*v1.x + v1.y*v1.y + v1.z*v1.z + v1.w*v1.w;
#pragma unroll
    for (int of = 16; of > 0; of >>= 1) {
        s  += __shfl_xor_sync(0xffffffffu, s,  of);
        sq += __shfl_xor_sync(0xffffffffu, sq, of);
    }
    float mean = s * (1.0f / CDIM);
    float var  = sq * (1.0f / CDIM) - mean * mean;
    float rstd = rsqrtf(var + 1e-5f);
    const float4* g4 = reinterpret_cast<const float4*>(gam);
    const float4* b4 = reinterpret_cast<const float4*>(bet);
    float r[8];
    {
        float4 ga = g4[lane * 2],     ba = b4[lane * 2];
        float4 gb = g4[lane * 2 + 1], bb = b4[lane * 2 + 1];
        r[0] = (v0.x - mean) * rstd * ga.x + ba.x;
        r[1] = (v0.y - mean) * rstd * ga.y + ba.y;
        r[2] = (v0.z - mean) * rstd * ga.z + ba.z;
        r[3] = (v0.w - mean) * rstd * ga.w + ba.w;
        r[4] = (v1.x - mean) * rstd * gb.x + bb.x;
        r[5] = (v1.y - mean) * rstd * gb.y + bb.y;
        r[6] = (v1.z - mean) * rstd * gb.z + bb.z;
        r[7] = (v1.w - mean) * rstd * gb.w + bb.w;
    }
    size_t base = (size_t)token * CDIM + lane * 8;
#pragma unroll
    for (int i = 0; i < 8; i += 2)
        *reinterpret_cast<__half2*>(o + base + i) =
            __floats2half2_rn(r[i], r[i + 1]);
}

// ================= warp-MMA GEMM ==============================
enum { EP_QKV = 0, EP_RESID = 2, EP_GELU = 3 };

__device__ __forceinline__ float gelu_exact(float v) {
    return 0.5f * v * (1.0f + erff(v * 0.70710678118654752f));
}

#define STAGE_BYTES 24576
#define B_OFF       16384

template <int EPI>
__global__ void __launch_bounds__(256) mm_mma(const __half* __restrict__ A,
                                              const __half* __restrict__ B,
                                              const float* __restrict__ bias,
                                              float* __restrict__ Cout,
                                              const float* __restrict__ Res,
                                              __half* __restrict__ OutH,
                                              const float* __restrict__ b_off,
                                              const float* __restrict__ b_attn,
                                              float* __restrict__ OA,
                                              int K, int Nvalid, int ldc)
{
    extern __shared__ __align__(128) char smem[];
    const uint32_t sb = smem_u32(smem);
    const int tid = threadIdx.x;
    const int wid = tid >> 5, l = tid & 31;
    const int wm = wid & 3, wn = wid >> 2;
    const int m0 = blockIdx.y * 128, n0 = blockIdx.x * 64;

    float acc[2][4][4];
#pragma unroll
    for (int i = 0; i < 2; i++)
#pragma unroll
        for (int j = 0; j < 4; j++)
#pragma unroll
            for (int q = 0; q < 4; q++) acc[i][j][q] = 0.0f;

    const int KC = K >> 6;

    auto load_stage = [&](int kcidx) {
        int k0 = kcidx << 6;
        uint32_t st = sb + (kcidx & 1) * STAGE_BYTES;
#pragma unroll
        for (int i = 0; i < 4; i++) {
            int id = tid + i * 256;
            int r = id >> 3, c = id & 7;
            cp16(st + r * 128 + ((c ^ (r & 7)) << 4),
                 A + (size_t)(m0 + r) * K + k0 + c * 8);
        }
#pragma unroll
        for (int i = 0; i < 2; i++) {
            int id = tid + i * 256;
            int r = id >> 3, c = id & 7;
            cp16(st + B_OFF + r * 128 + ((c ^ (r & 7)) << 4),
                 B + (size_t)(n0 + r) * K + k0 + c * 8);
        }
        CP_COMMIT();
    };

    load_stage(0);

    const int rowA = wm * 32 + (l & 15);
    const int cxA  = l >> 4;
    const int rowB = wn * 32 + (l & 7) + ((l >> 4) << 3);
    const int cxB  = (l >> 3) & 1;

    for (int kc = 0; kc < KC; kc++) {
        if (kc + 1 < KC) {
            load_stage(kc + 1);
            CP_WAIT(1);
        } else {
            CP_WAIT(0);
        }
        __syncthreads();

        uint32_t ab = sb + (kc & 1) * STAGE_BYTES;
        uint32_t bb = ab + B_OFF;
#pragma unroll
        for (int ks = 0; ks < 4; ks++) {
            uint32_t a[2][4], b[2][4];
#pragma unroll
            for (int mt = 0; mt < 2; mt++) {
                int row = rowA + mt * 16;
                ldm4(a[mt], ab + row * 128 + (((ks * 2 + cxA) ^ (row & 7)) << 4));
            }
#pragma unroll
            for (int ntp = 0; ntp < 2; ntp++) {
                int row = rowB + ntp * 16;
                ldm4(b[ntp], bb + row * 128 + (((ks * 2 + cxB) ^ (row & 7)) << 4));
            }
#pragma unroll
            for (int mt = 0; mt < 2; mt++)
#pragma unroll
                for (int nt = 0; nt < 4; nt++)
                    mma_f16(acc[mt][nt], a[mt], &b[nt >> 1][(nt & 1) * 2]);
        }
        __syncthreads();
    }

    // ---- epilogue ----
#pragma unroll
    for (int mt = 0; mt < 2; mt++) {
#pragma unroll
        for (int nt = 0; nt < 4; nt++) {
            int col = n0 + wn * 32 + nt * 8 + (l & 3) * 2;
            if (col >= Nvalid) continue;
#pragma unroll
            for (int half = 0; half < 2; half++) {
                int row = m0 + wm * 32 + mt * 16 + (l >> 2) + half * 8;
                float v0 = acc[mt][nt][half * 2];
                float v1 = acc[mt][nt][half * 2 + 1];
                if (EPI == EP_QKV) {
                    if (col < 256) {
                        float2 bv = *reinterpret_cast<const float2*>(bias + col);
                        v0 += bv.x; v1 += bv.y;
                        int n = row / LQ, li = row - n * LQ;
                        int h = col >> 5, d = col & 31;
                        *reinterpret_cast<__half2*>(OutH +
                            ((size_t)((n * NHEADS + h) * LQ + li)) * DH + d) =
                            __floats2half2_rn(v0, v1);
                    } else if (col < 656) {
                        float2 bv = *reinterpret_cast<const float2*>(b_off + (col - 256));
                        v0 += bv.x; v1 += bv.y;
                        *reinterpret_cast<float2*>(OA + (size_t)row * OA_LD + (col - 256)) =
                            make_float2(v0, v1);
                    } else {
                        float2 bv = *reinterpret_cast<const float2*>(b_attn + (col - 656));
                        v0 += bv.x; v1 += bv.y;
                        *reinterpret_cast<float2*>(OA + (size_t)row * OA_LD + 400 + (col - 656)) =
                            make_float2(v0, v1);
                    }
                } else {
                    float2 bv = *reinterpret_cast<const float2*>(bias + col);
                    v0 += bv.x; v1 += bv.y;
                    if (EPI == EP_RESID) {
                        float2 r = *reinterpret_cast<const float2*>(Res + (size_t)row * ldc + col);
                        v0 += r.x; v1 += r.y;
                        *reinterpret_cast<float2*>(Cout + (size_t)row * ldc + col) =
                            make_float2(v0, v1);
                    }
                    if (EPI == EP_GELU) {
                        v0 = gelu_exact(v0);
                        v1 = gelu_exact(v1);
                        *reinterpret_cast<__half2*>(OutH + (size_t)row * ldc + col) =
                            __floats2half2_rn(v0, v1);
                    }
                }
            }
        }
    }
}

// ======== sampling v2: warp = (token, 4 heads); 8 lanes/head; 4 ch/lane =====
__global__ void __launch_bounds__(256) sample_kernel(const float* __restrict__ refp)
{
    int warpId = blockIdx.x * 8 + (threadIdx.x >> 5);   // < NLTOK*2
    int lane = threadIdx.x & 31;
    int token = warpId >> 1;
    int hq = lane >> 3;                 // 0..3
    int hl = lane & 7;                  // 0..7 -> channels hl*4 .. hl*4+3
    int h = (warpId & 1) * 4 + hq;
    int n = token / LQ;

    const float* oa = g_oa + (size_t)token * OA_LD;

    // softmax over 25 logits with 8 lanes: lane holds p = hl, hl+8, hl+16, (24)
    const float* lg = oa + 400 + h * NPTS;
    float l0 = __ldg(lg + hl);
    float l1 = __ldg(lg + hl + 8);
    float l2 = __ldg(lg + hl + 16);
    float l3 = (hl == 0) ? __ldg(lg + 24) : -1e30f;
    float mx = fmaxf(fmaxf(l0, l1), fmaxf(l2, l3));
#pragma unroll
    for (int o = 4; o > 0; o >>= 1)
        mx = fmaxf(mx, __shfl_xor_sync(0xffffffffu, mx, o, 8));
    float w0 = expf(l0 - mx), w1 = expf(l1 - mx), w2 = expf(l2 - mx);
    float w3 = (hl == 0) ? expf(l3 - mx) : 0.0f;
    float ssum = w0 + w1 + w2 + w3;
#pragma unroll
    for (int o = 4; o > 0; o >>= 1)
        ssum += __shfl_xor_sync(0xffffffffu, ssum, o, 8);
    float inv = 1.0f / ssum;
    w0 *= inv; w1 *= inv; w2 *= inv; w3 *= inv;

    float2 rp = __ldg(reinterpret_cast<const float2*>(refp) + token);
    float gxb = fmaf(rp.x, (float)WDIM, -0.5f);
    float gyb = fmaf(rp.y, (float)HDIM, -0.5f);

    const float2* offp = reinterpret_cast<const float2*>(oa + h * (NPTS * 2));
    const char* vbase = reinterpret_cast<const char*>(
        g_val + ((size_t)(n * NHEADS + h) * LQ) * DH) + hl * 8;

    float2 accA = make_float2(0.f, 0.f);
    float2 accB = make_float2(0.f, 0.f);
#pragma unroll 1
    for (int p = 0; p < NPTS; p++) {
        float2 o2 = __ldg(offp + p);
        float src = (p < 8) ? w0 : (p < 16) ? w1 : (p < 24) ? w2 : w3;
        float aw = __shfl_sync(0xffffffffu, src, p & 7, 8);
        float gx = gxb + o2.x;
        float gy = gyb + o2.y;
        float fx0 = floorf(gx), fy0 = floorf(gy);
        float fx = gx - fx0, fy = gy - fy0;
        int x0 = (int)fx0, y0 = (int)fy0;
        float t0 = (1.f - fy) * aw, t1 = fy * aw;
        float w00 = (1.f - fx) * t0, w10 = fx * t0;
        float w01 = (1.f - fx) * t1, w11 = fx * t1;
        bool interior = ((unsigned)x0 <= (unsigned)(WDIM - 2)) &&
                        ((unsigned)y0 <= (unsigned)(HDIM - 2));
        if (__all_sync(0xffffffffu, interior)) {
            const char* p00 = vbase + (y0 * WDIM + x0) * (DH * 2);
            uint2 v00 = *reinterpret_cast<const uint2*>(p00);
            uint2 v10 = *reinterpret_cast<const uint2*>(p00 + DH * 2);
            uint2 v01 = *reinterpret_cast<const uint2*>(p00 + WDIM * DH * 2);
            uint2 v11 = *reinterpret_cast<const uint2*>(p00 + (WDIM + 1) * DH * 2);
            __half2 h00 = __floats2half2_rn(w00, w00);
            __half2 h10 = __floats2half2_rn(w10, w10);
            __half2 h01 = __floats2half2_rn(w01, w01);
            __half2 h11 = __floats2half2_rn(w11, w11);
            __half2 sA = __hmul2(*reinterpret_cast<__half2*>(&v00.x), h00);
            __half2 sB = __hmul2(*reinterpret_cast<__half2*>(&v00.y), h00);
            sA = __hfma2(*reinterpret_cast<__half2*>(&v10.x), h10, sA);
            sB = __hfma2(*reinterpret_cast<__half2*>(&v10.y), h10, sB);
            sA = __hfma2(*reinterpret_cast<__half2*>(&v01.x), h01, sA);
            sB = __hfma2(*reinterpret_cast<__half2*>(&v01.y), h01, sB);
            sA = __hfma2(*reinterpret_cast<__half2*>(&v11.x), h11, sA);
            sB = __hfma2(*reinterpret_cast<__half2*>(&v11.y), h11, sB);
            float2 fA = __half22float2(sA), fB = __half22float2(sB);
            accA.x += fA.x; accA.y += fA.y;
            accB.x += fB.x; accB.y += fB.y;
        } else {
            bool xv0 = (x0 >= 0) && (x0 < WDIM);
            bool xv1 = (x0 + 1 >= 0) && (x0 + 1 < WDIM);
            bool yv0 = (y0 >= 0) && (y0 < HDIM);
            bool yv1 = (y0 + 1 >= 0) && (y0 + 1 < HDIM);
#pragma unroll
            for (int tp = 0; tp < 4; tp++) {
                int xi = x0 + (tp & 1), yi = y0 + (tp >> 1);
                bool valid = (tp & 1 ? xv1 : xv0) && (tp >> 1 ? yv1 : yv0);
                float w = (tp == 0) ? w00 : (tp == 1) ? w10 : (tp == 2) ? w01 : w11;
                if (valid) {
                    uint2 v = *reinterpret_cast<const uint2*>(
                        vbase + (yi * WDIM + xi) * (DH * 2));
                    float2 fA = __half22float2(*reinterpret_cast<__half2*>(&v.x));
                    float2 fB = __half22float2(*reinterpret_cast<__half2*>(&v.y));
                    accA.x = fmaf(w, fA.x, accA.x);
                    accA.y = fmaf(w, fA.y, accA.y);
                    accB.x = fmaf(w, fB.x, accB.x);
                    accB.y = fmaf(w, fB.y, accB.y);
                }
            }
        }
    }
    __half2 oA = __floats2half2_rn(accA.x, accA.y);
    __half2 oB = __floats2half2_rn(accB.x, accB.y);
    uint2 ov;
    ov.x = *reinterpret_cast<uint32_t*>(&oA);
    ov.y = *reinterpret_cast<uint32_t*>(&oB);
    *reinterpret_cast<uint2*>(g_at + (size_t)token * CDIM + h * DH + hl * 4) = ov;
}

// ================= launch =================
extern "C" void kernel_launch(void* const* d_in, const int* in_sizes, int n_in,
                              void* d_out, int out_size)
{
    (void)in_sizes; (void)n_in; (void)out_size;
    const float* x      = (const float*)d_in[0];
    const float* refp   = (const float*)d_in[1];
    const float* ln1g   = (const float*)d_in[4];
    const float* ln1b   = (const float*)d_in[5];
    const float* w_off  = (const float*)d_in[6];
    const float* b_off  = (const float*)d_in[7];
    const float* w_attn = (const float*)d_in[8];
    const float* b_attn = (const float*)d_in[9];
    const float* w_val  = (const float*)d_in[10];
    const float* b_val  = (const float*)d_in[11];
    const float* w_out  = (const float*)d_in[12];
    const float* b_out  = (const float*)d_in[13];
    const float* ln2g   = (const float*)d_in[14];
    const float* ln2b   = (const float*)d_in[15];
    const float* w_fc1  = (const float*)d_in[16];
    const float* b_fc1  = (const float*)d_in[17];
    const float* w_fc2  = (const float*)d_in[18];
    const float* b_fc2  = (const float*)d_in[19];
    float* out = (float*)d_out;

    __half *q, *at, *q2, *h1, *wq, *wu, *w1, *w2, *pval;
    float *poa, *px1;
    cudaGetSymbolAddress((void**)&q,  g_q);   cudaGetSymbolAddress((void**)&at, g_at);
    cudaGetSymbolAddress((void**)&q2, g_q2);  cudaGetSymbolAddress((void**)&h1, g_h1);
    cudaGetSymbolAddress((void**)&wq, g_wq);  cudaGetSymbolAddress((void**)&wu, g_wu);
    cudaGetSymbolAddress((void**)&w1, g_w1);  cudaGetSymbolAddress((void**)&w2, g_w2);
    cudaGetSymbolAddress((void**)&pval, g_val);
    cudaGetSymbolAddress((void**)&poa,  g_oa);
    cudaGetSymbolAddress((void**)&px1,  g_x1);

    const int SM_TOT = 2 * STAGE_BYTES;   // 48KB
    cudaFuncSetAttribute(mm_mma<EP_QKV>,   cudaFuncAttributeMaxDynamicSharedMemorySize, SM_TOT);
    cudaFuncSetAttribute(mm_mma<EP_RESID>, cudaFuncAttributeMaxDynamicSharedMemorySize, SM_TOT);
    cudaFuncSetAttribute(mm_mma<EP_GELU>,  cudaFuncAttributeMaxDynamicSharedMemorySize, SM_TOT);

    dim3 blk(256);
    const int MT = NLTOK / 128;   // 144

    wprep_all<<<808, blk>>>(w_val, w_off, w_attn, w_out, w_fc1, w_fc2, wq, wu, w1, w2);
    ln_kernel<<<NLTOK / 8, blk>>>(x, ln1g, ln1b, q);
    mm_mma<EP_QKV><<<dim3(14, MT), blk, SM_TOT>>>(q, wq, b_val, nullptr, nullptr, pval,
                                                  b_off, b_attn, poa, 256, 856, 0);
    sample_kernel<<<(NLTOK * 2) / 8, blk>>>(refp);
    mm_mma<EP_RESID><<<dim3(4, MT), blk, SM_TOT>>>(at, wu, b_out, px1, x, nullptr,
                                                   nullptr, nullptr, nullptr, 256, 256, 256);
    ln_kernel<<<NLTOK / 8, blk>>>(px1, ln2g, ln2b, q2);
    mm_mma<EP_GELU><<<dim3(16, MT), blk, SM_TOT>>>(q2, w1, b_fc1, nullptr, nullptr, h1,
                                                   nullptr, nullptr, nullptr, 256, 1024, 1024);
    mm_mma<EP_RESID><<<dim3(4, MT), blk, SM_TOT>>>(h1, w2, b_fc2, out, px1, nullptr,
                                                   nullptr, nullptr, nullptr, 1024, 256, 256);
}